// round 8
// baseline (speedup 1.0000x reference)
#include <cuda_runtime.h>
#include <cuda_bf16.h>
#include <cstdint>

// Problem shape (fixed)
#define Bb    4
#define T     1024
#define E     512
#define H     8
#define MTOT  (Bb*T)       // 4096
#define NPROJ (H*E)        // 4096
#define BH    (Bb*H)       // 32

#define NEG_INF (__int_as_float(0xff800000))
#define QK_SCALE 0.21022410381342864f   // 512^-0.25

typedef __nv_bfloat16 bf16;

// ---------------- scratch (device globals; no allocs allowed) ----------------
__device__ __align__(16) bf16 g_xh[MTOT * E],   g_xl[MTOT * E];
__device__ __align__(16) bf16 g_wkh[NPROJ * E], g_wkl[NPROJ * E];
__device__ __align__(16) bf16 g_wqh[NPROJ * E], g_wql[NPROJ * E];
__device__ __align__(16) bf16 g_wvh[NPROJ * E], g_wvl[NPROJ * E];
__device__ __align__(16) bf16 g_wuh[E * NPROJ], g_wul[E * NPROJ];
__device__ __align__(16) bf16 g_qh[MTOT * NPROJ], g_ql[MTOT * NPROJ];  // pre-scaled
__device__ __align__(16) bf16 g_kh[MTOT * NPROJ], g_kl[MTOT * NPROJ];  // pre-scaled
__device__ __align__(16) bf16 g_vth[(size_t)BH * E * T], g_vtl[(size_t)BH * E * T]; // (b,h,e,t)
__device__ float g_s[(size_t)BH * T * T];
__device__ __align__(16) bf16 g_ph[(size_t)BH * T * T], g_pl[(size_t)BH * T * T];
__device__ __align__(16) bf16 g_aoh[MTOT * NPROJ], g_aol[MTOT * NPROJ];

// ---------------------------------------------------------------------------
__device__ __forceinline__ uint32_t smem_u32(const void* p) {
    uint32_t a;
    asm("{ .reg .u64 t; cvta.to.shared.u64 t, %1; cvt.u32.u64 %0, t; }" : "=r"(a) : "l"(p));
    return a;
}
__device__ __forceinline__ void cp16(uint32_t dst, const void* src) {
    asm volatile("cp.async.cg.shared.global [%0], [%1], 16;" :: "r"(dst), "l"(src) : "memory");
}
#define CP_COMMIT()  asm volatile("cp.async.commit_group;" ::: "memory")
#define CP_WAIT(n)   asm volatile("cp.async.wait_group %0;" :: "n"(n) : "memory")

__device__ __forceinline__ void ldsm4(uint32_t* r, uint32_t addr) {
    asm volatile("ldmatrix.sync.aligned.m8n8.x4.shared.b16 {%0,%1,%2,%3}, [%4];"
                 : "=r"(r[0]), "=r"(r[1]), "=r"(r[2]), "=r"(r[3]) : "r"(addr));
}
__device__ __forceinline__ void mma16816(float* c, const uint32_t* a, const uint32_t* b) {
    asm volatile(
        "mma.sync.aligned.m16n8k16.row.col.f32.bf16.bf16.f32 "
        "{%0,%1,%2,%3}, {%4,%5,%6,%7}, {%8,%9}, {%0,%1,%2,%3};"
        : "+f"(c[0]), "+f"(c[1]), "+f"(c[2]), "+f"(c[3])
        : "r"(a[0]), "r"(a[1]), "r"(a[2]), "r"(a[3]), "r"(b[0]), "r"(b[1]));
}

__device__ __forceinline__ void f32split(float x, bf16& h, bf16& l) {
    h = __float2bfloat16(x);
    l = __float2bfloat16(x - __bfloat162float(h));
}

// all 5 arrays are exactly MTOT*E = 2M elements: one merged launch
__global__ void split_all(const float* __restrict__ x,  const float* __restrict__ wk,
                          const float* __restrict__ wq, const float* __restrict__ wv,
                          const float* __restrict__ wu) {
    const int i = blockIdx.x * 256 + threadIdx.x;
    const float* s; bf16 *h, *l;
    switch (blockIdx.y) {
        case 0:  s = x;  h = g_xh;  l = g_xl;  break;
        case 1:  s = wk; h = g_wkh; l = g_wkl; break;
        case 2:  s = wq; h = g_wqh; l = g_wql; break;
        case 3:  s = wv; h = g_wvh; l = g_wvl; break;
        default: s = wu; h = g_wuh; l = g_wul; break;
    }
    f32split(s[i], h[i], l[i]);
}

// swizzled byte offset for (row, 16B-group kg) in a [rows][32]bf16 tile (64B rows)
__device__ __forceinline__ uint32_t swz(int row, int kg) {
    return row * 64 + ((kg ^ ((row >> 1) & 3)) << 4);
}

// ---------------------------------------------------------------------------
// GEMM core: C[BM,BN] = Ahi/lo[BM,K] x Bhi/lo[BN,K]^T (K-major, bf16x3)
// 256 threads, warp grid 4(m) x 2(n), warp tile BM/4 x BN/2.
// K-chunk 32, 3-stage cp.async, ONE __syncthreads per chunk:
//   wait(chunk i, allow i+1 in flight) ; sync ; prefetch(i+2) ; compute(i)
// Stage rotation (mod 3) means buffer (i+2)%3 was last read at iter i-1,
// which the sync at iter i certifies complete.
// ---------------------------------------------------------------------------
template<int BM, int BN>
__device__ __forceinline__ void tc_gemm(
    const bf16* __restrict__ Ah, const bf16* __restrict__ Al, int lda,
    const bf16* __restrict__ Bh, const bf16* __restrict__ Bl, int ldb,
    int K, float* acc)
{
    constexpr int WM = BM / 4, WN = BN / 2;
    constexpr int SA = BM * 64;          // bytes of one A array per stage
    constexpr int SB = BN * 64;
    constexpr int STG = 2 * (SA + SB);   // stage bytes
    extern __shared__ char sm[];

    const int tid  = threadIdx.x;
    const int lane = tid & 31;
    const int warp = tid >> 5;
    const int wm = warp >> 1, wn = warp & 1;

    // ldmatrix lane->element mapping
    const int arow = ((lane >> 3) & 1) * 8 + (lane & 7);
    const int akg  = (lane >> 4) & 1;
    const int brow = ((lane >> 4) & 1) * 8 + (lane & 7);
    const int bkg  = (lane >> 3) & 1;

    #pragma unroll
    for (int i = 0; i < WM * WN / 32; i++) acc[i] = 0.f;

    const int nch = K >> 5;

    auto load_chunk = [&](int i) {
        const int k0 = i << 5;
        const uint32_t st = smem_u32(sm + (i % 3) * STG);
        #pragma unroll
        for (int j = 0; j < BM / 64; j++) {          // BM*4 16B-chunks / 256 thr
            int idx = tid + j * 256;
            int r = idx >> 2, kg = idx & 3;
            uint32_t o = swz(r, kg);
            cp16(st + o,      Ah + (size_t)r * lda + k0 + kg * 8);
            cp16(st + SA + o, Al + (size_t)r * lda + k0 + kg * 8);
        }
        #pragma unroll
        for (int j = 0; j < BN / 64; j++) {
            int idx = tid + j * 256;
            int r = idx >> 2, kg = idx & 3;
            uint32_t o = swz(r, kg);
            cp16(st + 2 * SA + o,      Bh + (size_t)r * ldb + k0 + kg * 8);
            cp16(st + 2 * SA + SB + o, Bl + (size_t)r * ldb + k0 + kg * 8);
        }
        CP_COMMIT();
    };

    load_chunk(0);
    if (nch > 1) load_chunk(1);

    for (int i = 0; i < nch; i++) {
        if (i + 1 < nch) { CP_WAIT(1); } else { CP_WAIT(0); }
        __syncthreads();
        if (i + 2 < nch) load_chunk(i + 2);   // overlaps compute below

        const uint32_t st = smem_u32(sm + (i % 3) * STG);
        #pragma unroll
        for (int ks = 0; ks < 2; ks++) {
            uint32_t ah[WM / 16][4], al[WM / 16][4], bh[WN / 16][4], bl[WN / 16][4];
            #pragma unroll
            for (int im = 0; im < WM / 16; im++) {
                int row = wm * WM + im * 16 + arow;
                uint32_t o = swz(row, ks * 2 + akg);
                ldsm4(ah[im], st + o);
                ldsm4(al[im], st + SA + o);
            }
            #pragma unroll
            for (int j2 = 0; j2 < WN / 16; j2++) {
                int n = wn * WN + j2 * 16 + brow;
                uint32_t o = swz(n, ks * 2 + bkg);
                ldsm4(bh[j2], st + 2 * SA + o);
                ldsm4(bl[j2], st + 2 * SA + SB + o);
            }
            #pragma unroll
            for (int im = 0; im < WM / 16; im++)
                #pragma unroll
                for (int jn = 0; jn < WN / 8; jn++) {
                    float* c = acc + (im * (WN / 8) + jn) * 4;
                    const uint32_t* pbh = &bh[jn >> 1][(jn & 1) * 2];
                    const uint32_t* pbl = &bl[jn >> 1][(jn & 1) * 2];
                    mma16816(c, ah[im], pbh);
                    mma16816(c, ah[im], pbl);
                    mma16816(c, al[im], pbh);
                }
        }
    }
}

// epilogue iteration: f(row, col, val) over this thread's fragment elements
template<int BM, int BN, typename F>
__device__ __forceinline__ void epi(const float* acc, F&& f) {
    constexpr int WM = BM / 4, WN = BN / 2;
    const int lane = threadIdx.x & 31;
    const int warp = threadIdx.x >> 5;
    const int wm = warp >> 1, wn = warp & 1;
    const int g = lane >> 2, tg = lane & 3;
    #pragma unroll
    for (int im = 0; im < WM / 16; im++)
        #pragma unroll
        for (int jn = 0; jn < WN / 8; jn++)
            #pragma unroll
            for (int r = 0; r < 4; r++) {
                int row = wm * WM + im * 16 + g + ((r & 2) ? 8 : 0);
                int col = wn * WN + jn * 8 + tg * 2 + (r & 1);
                f(row, col, acc[(im * (WN / 8) + jn) * 4 + r]);
            }
}

// 128x128: stage 32KB x 3 = 96KB; 128x64: stage 24KB x 3 = 72KB
#define SMEM_BIG   (3 * 2 * (128 * 64 + 128 * 64))
#define SMEM_SMALL (3 * 2 * (128 * 64 + 64 * 64))

// ---------------------------------------------------------------------------
// QKV projection: BM=128, BN=128 (z: 0=k scaled, 1=q scaled, 2=v -> Vt)
// ---------------------------------------------------------------------------
__global__ __launch_bounds__(256, 2) void proj_kernel() {
    const int n0 = blockIdx.x * 128;
    const int m0 = blockIdx.y * 128;
    const int z  = blockIdx.z;
    const bf16* Wh = (z == 0) ? g_wkh : (z == 1) ? g_wqh : g_wvh;
    const bf16* Wl = (z == 0) ? g_wkl : (z == 1) ? g_wql : g_wvl;

    float acc[64];
    tc_gemm<128, 128>(g_xh + (size_t)m0 * E, g_xl + (size_t)m0 * E, E,
                      Wh + (size_t)n0 * E,  Wl + (size_t)n0 * E,  E, E, acc);

    if (z == 2) {
        epi<128, 128>(acc, [&](int row, int col, float v) {
            int m = m0 + row, n = n0 + col;
            int b = m >> 10, t = m & 1023, h = n >> 9, ec = n & 511;
            size_t o = ((size_t)((b * H + h) * E + ec)) * T + t;
            f32split(v, g_vth[o], g_vtl[o]);
        });
    } else {
        bf16* Dh = (z == 0) ? g_kh : g_qh;
        bf16* Dl = (z == 0) ? g_kl : g_ql;
        epi<128, 128>(acc, [&](int row, int col, float v) {
            size_t o = (size_t)(m0 + row) * NPROJ + n0 + col;
            f32split(v * QK_SCALE, Dh[o], Dl[o]);
        });
    }
}

// ---------------------------------------------------------------------------
// Scores: BM=128 (q), BN=128 (k); only tiles touching the lower triangle
// ---------------------------------------------------------------------------
__global__ __launch_bounds__(256, 2) void scores_kernel() {
    const int k0 = blockIdx.x * 128;
    const int q0 = blockIdx.y * 128;
    if (k0 > q0) return;
    const int bh = blockIdx.z;
    const int b = bh >> 3, h = bh & 7;
    const size_t base = (size_t)b * T * NPROJ + (size_t)h * E;

    float acc[64];
    tc_gemm<128, 128>(
        g_qh + base + (size_t)q0 * NPROJ, g_ql + base + (size_t)q0 * NPROJ, NPROJ,
        g_kh + base + (size_t)k0 * NPROJ, g_kl + base + (size_t)k0 * NPROJ, NPROJ,
        E, acc);

    float* S = g_s + (size_t)bh * T * T;
    epi<128, 128>(acc, [&](int row, int col, float v) {
        S[(size_t)(q0 + row) * T + k0 + col] = v;
    });
}

// ---------------------------------------------------------------------------
// Softmax row (valid keys [0, trow]): float4 loads, shuffle reductions,
// packed bf16x2 stores.  Writes only k < roundup128(trow+1).
// ---------------------------------------------------------------------------
__global__ void softmax_kernel() {
    const int row = blockIdx.x;
    const int trow = row & 1023;
    const int kend = (trow & ~127) + 128;
    const float4* __restrict__ S4 = (const float4*)(g_s + (size_t)row * T);
    bf16* __restrict__ Ph = g_ph + (size_t)row * T;
    bf16* __restrict__ Pl = g_pl + (size_t)row * T;
    const int tid = threadIdx.x;           // 256, each owns 4 consecutive
    const int lane = tid & 31, warp = tid >> 5;
    __shared__ float red[8];

    const int base = tid * 4;
    float4 s4 = S4[tid];
    float v[4] = { (base + 0 <= trow) ? s4.x : NEG_INF,
                   (base + 1 <= trow) ? s4.y : NEG_INF,
                   (base + 2 <= trow) ? s4.z : NEG_INF,
                   (base + 3 <= trow) ? s4.w : NEG_INF };

    float m = fmaxf(fmaxf(v[0], v[1]), fmaxf(v[2], v[3]));
    #pragma unroll
    for (int o = 16; o > 0; o >>= 1) m = fmaxf(m, __shfl_xor_sync(~0u, m, o));
    if (lane == 0) red[warp] = m;
    __syncthreads();
    m = red[0];
    #pragma unroll
    for (int w = 1; w < 8; w++) m = fmaxf(m, red[w]);
    __syncthreads();

    float sum = 0.f;
    #pragma unroll
    for (int i = 0; i < 4; i++) { v[i] = __expf(v[i] - m); sum += v[i]; }  // -inf -> 0
    #pragma unroll
    for (int o = 16; o > 0; o >>= 1) sum += __shfl_xor_sync(~0u, sum, o);
    if (lane == 0) red[warp] = sum;
    __syncthreads();
    sum = red[0];
    #pragma unroll
    for (int w = 1; w < 8; w++) sum += red[w];

    const float inv = 1.0f / sum;
    if (base < kend) {
        bf16 h[4], l[4];
        #pragma unroll
        for (int i = 0; i < 4; i++) f32split(v[i] * inv, h[i], l[i]);
        *(uint2*)(Ph + base) = *(const uint2*)h;
        *(uint2*)(Pl + base) = *(const uint2*)l;
    }
}

// ---------------------------------------------------------------------------
// AV: BM=128 (q), BN=128 (e); B operand = Vt, K = t truncated causally
// ---------------------------------------------------------------------------
__global__ __launch_bounds__(256, 2) void av_kernel() {
    const int n0 = blockIdx.x * 128;   // over E
    const int q0 = blockIdx.y * 128;
    const int bh = blockIdx.z;
    const int b = bh >> 3, h = bh & 7;
    const size_t pbase = (size_t)bh * T * T + (size_t)q0 * T;
    const size_t vbase = (size_t)bh * E * T + (size_t)n0 * T;

    float acc[64];
    tc_gemm<128, 128>(g_ph + pbase, g_pl + pbase, T,
                      g_vth + vbase, g_vtl + vbase, T,
                      q0 + 128, acc);

    epi<128, 128>(acc, [&](int row, int col, float v) {
        size_t o = (size_t)(b * T + q0 + row) * NPROJ + h * E + n0 + col;
        f32split(v, g_aoh[o], g_aol[o]);
    });
}

// ---------------------------------------------------------------------------
// Unify: BM=128, BN=64 (grid 8x32 keeps the chip filled); out = AO @ wu^T + bu
// ---------------------------------------------------------------------------
__global__ __launch_bounds__(256, 2) void unify_kernel(const float* __restrict__ bu,
                                                       float* __restrict__ out) {
    const int n0 = blockIdx.x * 64;    // over E
    const int m0 = blockIdx.y * 128;

    float acc[32];
    tc_gemm<128, 64>(g_aoh + (size_t)m0 * NPROJ, g_aol + (size_t)m0 * NPROJ, NPROJ,
                     g_wuh + (size_t)n0 * NPROJ, g_wul + (size_t)n0 * NPROJ, NPROJ,
                     NPROJ, acc);

    epi<128, 64>(acc, [&](int row, int col, float v) {
        out[(size_t)(m0 + row) * E + n0 + col] = v + bu[n0 + col];
    });
}

// ---------------------------------------------------------------------------
extern "C" void kernel_launch(void* const* d_in, const int* in_sizes, int n_in,
                              void* d_out, int out_size) {
    const float* x  = (const float*)d_in[0];
    const float* wk = (const float*)d_in[1];
    const float* wq = (const float*)d_in[2];
    const float* wv = (const float*)d_in[3];
    const float* wu = (const float*)d_in[4];
    const float* bu = (const float*)d_in[5];
    float* out = (float*)d_out;

    cudaFuncSetAttribute(proj_kernel,   cudaFuncAttributeMaxDynamicSharedMemorySize, SMEM_BIG);
    cudaFuncSetAttribute(scores_kernel, cudaFuncAttributeMaxDynamicSharedMemorySize, SMEM_BIG);
    cudaFuncSetAttribute(av_kernel,     cudaFuncAttributeMaxDynamicSharedMemorySize, SMEM_BIG);
    cudaFuncSetAttribute(unify_kernel,  cudaFuncAttributeMaxDynamicSharedMemorySize, SMEM_SMALL);

    split_all<<<dim3(MTOT * E / 256, 5), 256>>>(x, wk, wq, wv, wu);

    proj_kernel  <<<dim3(NPROJ / 128, MTOT / 128, 3), 256, SMEM_BIG>>>();
    scores_kernel<<<dim3(T / 128, T / 128, BH),        256, SMEM_BIG>>>();
    softmax_kernel<<<BH * T, 256>>>();
    av_kernel    <<<dim3(E / 128, T / 128, BH),        256, SMEM_BIG>>>();
    unify_kernel <<<dim3(E / 64, MTOT / 128),          256, SMEM_SMALL>>>(bu, out);
}

// round 9
// speedup vs baseline: 1.0770x; 1.0770x over previous
#include <cuda_runtime.h>
#include <cuda_bf16.h>
#include <cstdint>

// Problem shape (fixed)
#define Bb    4
#define T     1024
#define E     512
#define H     8
#define MTOT  (Bb*T)       // 4096
#define NPROJ (H*E)        // 4096
#define BH    (Bb*H)       // 32

#define NEG_INF (__int_as_float(0xff800000))
#define QK_SCALE 0.21022410381342864f   // 512^-0.25

typedef __nv_bfloat16 bf16;

// ---------------- scratch (device globals; no allocs allowed) ----------------
__device__ __align__(16) bf16 g_xh[MTOT * E],   g_xl[MTOT * E];
__device__ __align__(16) bf16 g_wkh[NPROJ * E], g_wkl[NPROJ * E];
__device__ __align__(16) bf16 g_wqh[NPROJ * E], g_wql[NPROJ * E];
__device__ __align__(16) bf16 g_wvh[NPROJ * E], g_wvl[NPROJ * E];
__device__ __align__(16) bf16 g_wuh[E * NPROJ], g_wul[E * NPROJ];
__device__ __align__(16) bf16 g_qh[MTOT * NPROJ], g_ql[MTOT * NPROJ];  // pre-scaled
__device__ __align__(16) bf16 g_kh[MTOT * NPROJ], g_kl[MTOT * NPROJ];  // pre-scaled
__device__ __align__(16) bf16 g_vth[(size_t)BH * E * T], g_vtl[(size_t)BH * E * T]; // (b,h,e,t)
__device__ float g_s[(size_t)BH * T * T];
__device__ __align__(16) bf16 g_ph[(size_t)BH * T * T], g_pl[(size_t)BH * T * T];
__device__ __align__(16) bf16 g_aoh[MTOT * NPROJ], g_aol[MTOT * NPROJ];

// ---------------------------------------------------------------------------
__device__ __forceinline__ uint32_t smem_u32(const void* p) {
    uint32_t a;
    asm("{ .reg .u64 t; cvta.to.shared.u64 t, %1; cvt.u32.u64 %0, t; }" : "=r"(a) : "l"(p));
    return a;
}
__device__ __forceinline__ void cp16(uint32_t dst, const void* src) {
    asm volatile("cp.async.cg.shared.global [%0], [%1], 16;" :: "r"(dst), "l"(src) : "memory");
}
#define CP_COMMIT()  asm volatile("cp.async.commit_group;" ::: "memory")
#define CP_WAIT(n)   asm volatile("cp.async.wait_group %0;" :: "n"(n) : "memory")

__device__ __forceinline__ void ldsm4(uint32_t* r, uint32_t addr) {
    asm volatile("ldmatrix.sync.aligned.m8n8.x4.shared.b16 {%0,%1,%2,%3}, [%4];"
                 : "=r"(r[0]), "=r"(r[1]), "=r"(r[2]), "=r"(r[3]) : "r"(addr));
}
__device__ __forceinline__ void mma16816(float* c, const uint32_t* a, const uint32_t* b) {
    asm volatile(
        "mma.sync.aligned.m16n8k16.row.col.f32.bf16.bf16.f32 "
        "{%0,%1,%2,%3}, {%4,%5,%6,%7}, {%8,%9}, {%0,%1,%2,%3};"
        : "+f"(c[0]), "+f"(c[1]), "+f"(c[2]), "+f"(c[3])
        : "r"(a[0]), "r"(a[1]), "r"(a[2]), "r"(a[3]), "r"(b[0]), "r"(b[1]));
}

__device__ __forceinline__ void f32split(float x, bf16& h, bf16& l) {
    h = __float2bfloat16(x);
    l = __float2bfloat16(x - __bfloat162float(h));
}

// all 5 arrays are exactly MTOT*E = 2M elements: one merged launch
__global__ void split_all(const float* __restrict__ x,  const float* __restrict__ wk,
                          const float* __restrict__ wq, const float* __restrict__ wv,
                          const float* __restrict__ wu) {
    const int i = blockIdx.x * 256 + threadIdx.x;
    const float* s; bf16 *h, *l;
    switch (blockIdx.y) {
        case 0:  s = x;  h = g_xh;  l = g_xl;  break;
        case 1:  s = wk; h = g_wkh; l = g_wkl; break;
        case 2:  s = wq; h = g_wqh; l = g_wql; break;
        case 3:  s = wv; h = g_wvh; l = g_wvl; break;
        default: s = wu; h = g_wuh; l = g_wul; break;
    }
    f32split(s[i], h[i], l[i]);
}

// SW128-style swizzle: 128B rows (64 bf16 of K per row), kg = 16B group 0..7
__device__ __forceinline__ uint32_t swz(int row, int kg) {
    return row * 128 + ((kg ^ (row & 7)) << 4);
}

// ---------------------------------------------------------------------------
// GEMM core (R7, proven): C[BM,BN] = Ahi/lo[BM,K] x Bhi/lo[BN,K]^T, bf16x3.
// 256 threads, warp grid 4(m) x 2(n), warp tile 32x32, K-chunk 64, 2-stage
// cp.async, ONE __syncthreads per chunk.
// ---------------------------------------------------------------------------
template<int BM, int BN>
__device__ __forceinline__ void tc_gemm(
    const bf16* __restrict__ Ah, const bf16* __restrict__ Al, int lda,
    const bf16* __restrict__ Bh, const bf16* __restrict__ Bl, int ldb,
    int K, float* acc)
{
    constexpr int WM = BM / 4, WN = BN / 2;
    constexpr int SA = BM * 128;         // bytes of one A array per stage
    constexpr int SB = BN * 128;
    constexpr int STG = 2 * SA + 2 * SB; // stage bytes
    extern __shared__ char sm[];

    const int tid  = threadIdx.x;
    const int lane = tid & 31;
    const int warp = tid >> 5;
    const int wm = warp >> 1, wn = warp & 1;

    const int arow = ((lane >> 3) & 1) * 8 + (lane & 7);
    const int akg  = (lane >> 4) & 1;
    const int brow = ((lane >> 4) & 1) * 8 + (lane & 7);
    const int bkg  = (lane >> 3) & 1;

    #pragma unroll
    for (int i = 0; i < WM * WN / 32; i++) acc[i] = 0.f;

    const int nch = K >> 6;

    auto load_chunk = [&](int i) {
        const int k0 = i << 6;
        const uint32_t st = smem_u32(sm + (i & 1) * STG);
        #pragma unroll
        for (int j = 0; j < BM / 32; j++) {
            int idx = tid + j * 256;
            int r = idx >> 3, kg = idx & 7;
            uint32_t o = swz(r, kg);
            cp16(st + o,      Ah + (size_t)r * lda + k0 + kg * 8);
            cp16(st + SA + o, Al + (size_t)r * lda + k0 + kg * 8);
        }
        #pragma unroll
        for (int j = 0; j < BN / 32; j++) {
            int idx = tid + j * 256;
            int r = idx >> 3, kg = idx & 7;
            uint32_t o = swz(r, kg);
            cp16(st + 2 * SA + o,      Bh + (size_t)r * ldb + k0 + kg * 8);
            cp16(st + 2 * SA + SB + o, Bl + (size_t)r * ldb + k0 + kg * 8);
        }
        CP_COMMIT();
    };

    load_chunk(0);

    for (int i = 0; i < nch; i++) {
        CP_WAIT(0);
        __syncthreads();
        if (i + 1 < nch) load_chunk(i + 1);

        const uint32_t st = smem_u32(sm + (i & 1) * STG);
        #pragma unroll
        for (int ks = 0; ks < 4; ks++) {
            uint32_t ah[WM / 16][4], al[WM / 16][4], bh[WN / 16][4], bl[WN / 16][4];
            #pragma unroll
            for (int im = 0; im < WM / 16; im++) {
                int row = wm * WM + im * 16 + arow;
                uint32_t o = swz(row, ks * 2 + akg);
                ldsm4(ah[im], st + o);
                ldsm4(al[im], st + SA + o);
            }
            #pragma unroll
            for (int j2 = 0; j2 < WN / 16; j2++) {
                int n = wn * WN + j2 * 16 + brow;
                uint32_t o = swz(n, ks * 2 + bkg);
                ldsm4(bh[j2], st + 2 * SA + o);
                ldsm4(bl[j2], st + 2 * SA + SB + o);
            }
            #pragma unroll
            for (int im = 0; im < WM / 16; im++)
                #pragma unroll
                for (int jn = 0; jn < WN / 8; jn++) {
                    float* c = acc + (im * (WN / 8) + jn) * 4;
                    const uint32_t* pbh = &bh[jn >> 1][(jn & 1) * 2];
                    const uint32_t* pbl = &bl[jn >> 1][(jn & 1) * 2];
                    mma16816(c, ah[im], pbh);
                    mma16816(c, ah[im], pbl);
                    mma16816(c, al[im], pbh);
                }
        }
    }
}

// epilogue iteration: f(row, col, val) over this thread's fragment elements
template<int BM, int BN, typename F>
__device__ __forceinline__ void epi(const float* acc, F&& f) {
    constexpr int WM = BM / 4, WN = BN / 2;
    const int lane = threadIdx.x & 31;
    const int warp = threadIdx.x >> 5;
    const int wm = warp >> 1, wn = warp & 1;
    const int g = lane >> 2, tg = lane & 3;
    #pragma unroll
    for (int im = 0; im < WM / 16; im++)
        #pragma unroll
        for (int jn = 0; jn < WN / 8; jn++)
            #pragma unroll
            for (int r = 0; r < 4; r++) {
                int row = wm * WM + im * 16 + g + ((r & 2) ? 8 : 0);
                int col = wn * WN + jn * 8 + tg * 2 + (r & 1);
                f(row, col, acc[(im * (WN / 8) + jn) * 4 + r]);
            }
}

// stage = 2*(128*128) + 2*(64*128) = 48 KB; 2 stages = 96 KB
#define SMEM_GEMM (2 * (2 * 128 * 128 + 2 * 64 * 128))

// ---------------------------------------------------------------------------
// QKV projection: BM=128, BN=64 (z: 0=k scaled, 1=q scaled, 2=v -> Vt).
// z==2 stages the tile through smem so the transposed Vt write is coalesced
// along t (direct fragment writes are stride-T 2B scatters).
// ---------------------------------------------------------------------------
__global__ __launch_bounds__(256, 2) void proj_kernel() {
    const int n0 = blockIdx.x * 64;
    const int m0 = blockIdx.y * 128;
    const int z  = blockIdx.z;
    const bf16* Wh = (z == 0) ? g_wkh : (z == 1) ? g_wqh : g_wvh;
    const bf16* Wl = (z == 0) ? g_wkl : (z == 1) ? g_wql : g_wvl;

    float acc[32];
    tc_gemm<128, 64>(g_xh + (size_t)m0 * E, g_xl + (size_t)m0 * E, E,
                     Wh + (size_t)n0 * E,  Wl + (size_t)n0 * E,  E, E, acc);

    if (z == 2) {
        extern __shared__ char sm[];
        float* smf = (float*)sm;              // 128 x 65 fp32 = 33.3 KB (reuse stages)
        __syncthreads();                      // all warps done reading stage smem
        epi<128, 64>(acc, [&](int row, int col, float v) {
            smf[row * 65 + col] = v;
        });
        __syncthreads();
        const int b = m0 >> 10, t_base = m0 & 1023;
        const int h = n0 >> 9,  ec_base = n0 & 511;
        const size_t vb = ((size_t)((b * H + h) * E + ec_base)) * T + t_base;
        const int tid = threadIdx.x;
        #pragma unroll
        for (int j = 0; j < 32; j++) {
            int idx = tid + j * 256;          // 8192 elements
            int ec_i = idx >> 7, t_i = idx & 127;
            float v = smf[t_i * 65 + ec_i];   // stride-65 read: conflict-free
            bf16 hh, ll; f32split(v, hh, ll);
            size_t o = vb + (size_t)ec_i * T + t_i;   // consecutive t_i -> coalesced
            g_vth[o] = hh; g_vtl[o] = ll;
        }
    } else {
        bf16* Dh = (z == 0) ? g_kh : g_qh;
        bf16* Dl = (z == 0) ? g_kl : g_ql;
        epi<128, 64>(acc, [&](int row, int col, float v) {
            size_t o = (size_t)(m0 + row) * NPROJ + n0 + col;
            f32split(v * QK_SCALE, Dh[o], Dl[o]);
        });
    }
}

// ---------------------------------------------------------------------------
// Scores: BM=128 (q), BN=64 (k); lower-triangle tiles only.
// q index reversed so longest q-blocks schedule first (wave balance).
// ---------------------------------------------------------------------------
__global__ __launch_bounds__(256, 2) void scores_kernel() {
    const int k0 = blockIdx.x * 64;
    const int q0 = (int)(gridDim.y - 1 - blockIdx.y) * 128;
    if (k0 >= q0 + 128) return;
    const int bh = blockIdx.z;
    const int b = bh >> 3, h = bh & 7;
    const size_t base = (size_t)b * T * NPROJ + (size_t)h * E;

    float acc[32];
    tc_gemm<128, 64>(
        g_qh + base + (size_t)q0 * NPROJ, g_ql + base + (size_t)q0 * NPROJ, NPROJ,
        g_kh + base + (size_t)k0 * NPROJ, g_kl + base + (size_t)k0 * NPROJ, NPROJ,
        E, acc);

    float* S = g_s + (size_t)bh * T * T;
    epi<128, 64>(acc, [&](int row, int col, float v) {
        S[(size_t)(q0 + row) * T + k0 + col] = v;
    });
}

// ---------------------------------------------------------------------------
// Softmax (R8, proven): float4 loads, shuffle reductions, packed bf16x2 stores.
// Writes only k < roundup128(trow+1) — av never reads past the diagonal tile.
// ---------------------------------------------------------------------------
__global__ void softmax_kernel() {
    const int row = blockIdx.x;
    const int trow = row & 1023;
    const int kend = (trow & ~127) + 128;
    const float4* __restrict__ S4 = (const float4*)(g_s + (size_t)row * T);
    bf16* __restrict__ Ph = g_ph + (size_t)row * T;
    bf16* __restrict__ Pl = g_pl + (size_t)row * T;
    const int tid = threadIdx.x;           // 256, each owns 4 consecutive
    const int lane = tid & 31, warp = tid >> 5;
    __shared__ float red[8];

    const int base = tid * 4;
    float4 s4 = S4[tid];
    float v[4] = { (base + 0 <= trow) ? s4.x : NEG_INF,
                   (base + 1 <= trow) ? s4.y : NEG_INF,
                   (base + 2 <= trow) ? s4.z : NEG_INF,
                   (base + 3 <= trow) ? s4.w : NEG_INF };

    float m = fmaxf(fmaxf(v[0], v[1]), fmaxf(v[2], v[3]));
    #pragma unroll
    for (int o = 16; o > 0; o >>= 1) m = fmaxf(m, __shfl_xor_sync(~0u, m, o));
    if (lane == 0) red[warp] = m;
    __syncthreads();
    m = red[0];
    #pragma unroll
    for (int w = 1; w < 8; w++) m = fmaxf(m, red[w]);
    __syncthreads();

    float sum = 0.f;
    #pragma unroll
    for (int i = 0; i < 4; i++) { v[i] = __expf(v[i] - m); sum += v[i]; }  // -inf -> 0
    #pragma unroll
    for (int o = 16; o > 0; o >>= 1) sum += __shfl_xor_sync(~0u, sum, o);
    if (lane == 0) red[warp] = sum;
    __syncthreads();
    sum = red[0];
    #pragma unroll
    for (int w = 1; w < 8; w++) sum += red[w];

    const float inv = 1.0f / sum;
    if (base < kend) {
        bf16 h[4], l[4];
        #pragma unroll
        for (int i = 0; i < 4; i++) f32split(v[i] * inv, h[i], l[i]);
        *(uint2*)(Ph + base) = *(const uint2*)h;
        *(uint2*)(Pl + base) = *(const uint2*)l;
    }
}

// ---------------------------------------------------------------------------
// AV: BM=128 (q), BN=64 (e); B operand = Vt, K truncated causally.
// q index reversed: K=1024 blocks run first, K=128 stragglers fill the tail.
// ---------------------------------------------------------------------------
__global__ __launch_bounds__(256, 2) void av_kernel() {
    const int n0 = blockIdx.x * 64;    // over E
    const int q0 = (int)(gridDim.y - 1 - blockIdx.y) * 128;
    const int bh = blockIdx.z;
    const int b = bh >> 3, h = bh & 7;
    const size_t pbase = (size_t)bh * T * T + (size_t)q0 * T;
    const size_t vbase = (size_t)bh * E * T + (size_t)n0 * T;

    float acc[32];
    tc_gemm<128, 64>(g_ph + pbase, g_pl + pbase, T,
                     g_vth + vbase, g_vtl + vbase, T,
                     q0 + 128, acc);

    epi<128, 64>(acc, [&](int row, int col, float v) {
        size_t o = (size_t)(b * T + q0 + row) * NPROJ + h * E + n0 + col;
        f32split(v, g_aoh[o], g_aol[o]);
    });
}

// ---------------------------------------------------------------------------
// Unify: BM=128, BN=64; out = AO @ wu^T + bu
// ---------------------------------------------------------------------------
__global__ __launch_bounds__(256, 2) void unify_kernel(const float* __restrict__ bu,
                                                       float* __restrict__ out) {
    const int n0 = blockIdx.x * 64;    // over E
    const int m0 = blockIdx.y * 128;

    float acc[32];
    tc_gemm<128, 64>(g_aoh + (size_t)m0 * NPROJ, g_aol + (size_t)m0 * NPROJ, NPROJ,
                     g_wuh + (size_t)n0 * NPROJ, g_wul + (size_t)n0 * NPROJ, NPROJ,
                     NPROJ, acc);

    epi<128, 64>(acc, [&](int row, int col, float v) {
        out[(size_t)(m0 + row) * E + n0 + col] = v + bu[n0 + col];
    });
}

// ---------------------------------------------------------------------------
extern "C" void kernel_launch(void* const* d_in, const int* in_sizes, int n_in,
                              void* d_out, int out_size) {
    const float* x  = (const float*)d_in[0];
    const float* wk = (const float*)d_in[1];
    const float* wq = (const float*)d_in[2];
    const float* wv = (const float*)d_in[3];
    const float* wu = (const float*)d_in[4];
    const float* bu = (const float*)d_in[5];
    float* out = (float*)d_out;

    cudaFuncSetAttribute(proj_kernel,   cudaFuncAttributeMaxDynamicSharedMemorySize, SMEM_GEMM);
    cudaFuncSetAttribute(scores_kernel, cudaFuncAttributeMaxDynamicSharedMemorySize, SMEM_GEMM);
    cudaFuncSetAttribute(av_kernel,     cudaFuncAttributeMaxDynamicSharedMemorySize, SMEM_GEMM);
    cudaFuncSetAttribute(unify_kernel,  cudaFuncAttributeMaxDynamicSharedMemorySize, SMEM_GEMM);

    split_all<<<dim3(MTOT * E / 256, 5), 256>>>(x, wk, wq, wv, wu);

    proj_kernel  <<<dim3(NPROJ / 64, MTOT / 128, 3), 256, SMEM_GEMM>>>();
    scores_kernel<<<dim3(T / 64, T / 128, BH),        256, SMEM_GEMM>>>();
    softmax_kernel<<<BH * T, 256>>>();
    av_kernel    <<<dim3(E / 64, T / 128, BH),        256, SMEM_GEMM>>>();
    unify_kernel <<<dim3(E / 64, MTOT / 128),         256, SMEM_GEMM>>>(bu, out);
}

// round 10
// speedup vs baseline: 1.5858x; 1.4724x over previous
#include <cuda_runtime.h>
#include <cuda_fp16.h>
#include <cstdint>

// Problem shape (fixed)
#define Bb    4
#define T     1024
#define E     512
#define H     8
#define MTOT  (Bb*T)       // 4096
#define NPROJ (H*E)        // 4096
#define BH    (Bb*H)       // 32

#define NEG_INF (__int_as_float(0xff800000))
#define QK_SCALE 0.21022410381342864f   // 512^-0.25

typedef __half f16;

// ---------------- scratch (device globals; no allocs allowed) ----------------
__device__ __align__(16) f16 g_x[MTOT * E];                          // single
__device__ __align__(16) f16 g_wkh[NPROJ * E], g_wkl[NPROJ * E];
__device__ __align__(16) f16 g_wqh[NPROJ * E], g_wql[NPROJ * E];
__device__ __align__(16) f16 g_wvh[NPROJ * E], g_wvl[NPROJ * E];
__device__ __align__(16) f16 g_wuh[E * NPROJ], g_wul[E * NPROJ];
__device__ __align__(16) f16 g_q[MTOT * NPROJ];                      // single, pre-scaled
__device__ __align__(16) f16 g_kh[MTOT * NPROJ], g_kl[MTOT * NPROJ]; // dual, pre-scaled
__device__ __align__(16) f16 g_vth[(size_t)BH * E * T], g_vtl[(size_t)BH * E * T]; // (b,h,e,t)
__device__ float g_s[(size_t)BH * T * T];
__device__ __align__(16) f16 g_p[(size_t)BH * T * T];                // single probs
__device__ __align__(16) f16 g_ao[MTOT * NPROJ];                     // single

// ---------------------------------------------------------------------------
__device__ __forceinline__ uint32_t smem_u32(const void* p) {
    uint32_t a;
    asm("{ .reg .u64 t; cvta.to.shared.u64 t, %1; cvt.u32.u64 %0, t; }" : "=r"(a) : "l"(p));
    return a;
}
__device__ __forceinline__ void cp16(uint32_t dst, const void* src) {
    asm volatile("cp.async.cg.shared.global [%0], [%1], 16;" :: "r"(dst), "l"(src) : "memory");
}
#define CP_COMMIT()  asm volatile("cp.async.commit_group;" ::: "memory")
#define CP_WAIT(n)   asm volatile("cp.async.wait_group %0;" :: "n"(n) : "memory")

__device__ __forceinline__ void ldsm4(uint32_t* r, uint32_t addr) {
    asm volatile("ldmatrix.sync.aligned.m8n8.x4.shared.b16 {%0,%1,%2,%3}, [%4];"
                 : "=r"(r[0]), "=r"(r[1]), "=r"(r[2]), "=r"(r[3]) : "r"(addr));
}
__device__ __forceinline__ void mma16816(float* c, const uint32_t* a, const uint32_t* b) {
    asm volatile(
        "mma.sync.aligned.m16n8k16.row.col.f32.f16.f16.f32 "
        "{%0,%1,%2,%3}, {%4,%5,%6,%7}, {%8,%9}, {%0,%1,%2,%3};"
        : "+f"(c[0]), "+f"(c[1]), "+f"(c[2]), "+f"(c[3])
        : "r"(a[0]), "r"(a[1]), "r"(a[2]), "r"(a[3]), "r"(b[0]), "r"(b[1]));
}

__device__ __forceinline__ void f16split(float x, f16& h, f16& l) {
    h = __float2half(x);
    l = __float2half(x - __half2float(h));
}

// x -> single fp16; 4 weight mats -> fp16 hi/lo.  All are 2M elements.
__global__ void split_all(const float* __restrict__ x,  const float* __restrict__ wk,
                          const float* __restrict__ wq, const float* __restrict__ wv,
                          const float* __restrict__ wu) {
    const int i = blockIdx.x * 256 + threadIdx.x;
    if (blockIdx.y == 0) { g_x[i] = __float2half(x[i]); return; }
    const float* s; f16 *h, *l;
    switch (blockIdx.y) {
        case 1:  s = wk; h = g_wkh; l = g_wkl; break;
        case 2:  s = wq; h = g_wqh; l = g_wql; break;
        case 3:  s = wv; h = g_wvh; l = g_wvl; break;
        default: s = wu; h = g_wuh; l = g_wul; break;
    }
    f16split(s[i], h[i], l[i]);
}

// SW128-style swizzle: 128B rows (64 f16 of K per row), kg = 16B group 0..7
__device__ __forceinline__ uint32_t swz(int row, int kg) {
    return row * 128 + ((kg ^ (row & 7)) << 4);
}

// ---------------------------------------------------------------------------
// GEMM core (fp16 2-mma): C[BM,BN] = A[BM,K] x (Bh+Bl)[BN,K]^T.
// A single fp16, B split hi/lo.  256 threads, warp grid 4(m) x 2(n),
// warp tile 32x32, K-chunk 64, 2-stage cp.async, ONE __syncthreads per chunk.
// ---------------------------------------------------------------------------
template<int BM, int BN>
__device__ __forceinline__ void tc_gemm(
    const f16* __restrict__ A, int lda,
    const f16* __restrict__ Bh, const f16* __restrict__ Bl, int ldb,
    int K, float* acc)
{
    constexpr int WM = BM / 4, WN = BN / 2;
    constexpr int SA = BM * 128;          // A array bytes per stage
    constexpr int SB = BN * 128;          // one B array bytes per stage
    constexpr int STG = SA + 2 * SB;      // stage bytes
    extern __shared__ char sm[];

    const int tid  = threadIdx.x;
    const int lane = tid & 31;
    const int warp = tid >> 5;
    const int wm = warp >> 1, wn = warp & 1;

    const int arow = ((lane >> 3) & 1) * 8 + (lane & 7);
    const int akg  = (lane >> 4) & 1;
    const int brow = ((lane >> 4) & 1) * 8 + (lane & 7);
    const int bkg  = (lane >> 3) & 1;

    #pragma unroll
    for (int i = 0; i < WM * WN / 32; i++) acc[i] = 0.f;

    const int nch = K >> 6;

    auto load_chunk = [&](int i) {
        const int k0 = i << 6;
        const uint32_t st = smem_u32(sm + (i & 1) * STG);
        #pragma unroll
        for (int j = 0; j < BM / 32; j++) {
            int idx = tid + j * 256;
            int r = idx >> 3, kg = idx & 7;
            cp16(st + swz(r, kg), A + (size_t)r * lda + k0 + kg * 8);
        }
        #pragma unroll
        for (int j = 0; j < BN / 32; j++) {
            int idx = tid + j * 256;
            int r = idx >> 3, kg = idx & 7;
            uint32_t o = swz(r, kg);
            cp16(st + SA + o,      Bh + (size_t)r * ldb + k0 + kg * 8);
            cp16(st + SA + SB + o, Bl + (size_t)r * ldb + k0 + kg * 8);
        }
        CP_COMMIT();
    };

    load_chunk(0);

    for (int i = 0; i < nch; i++) {
        CP_WAIT(0);
        __syncthreads();
        if (i + 1 < nch) load_chunk(i + 1);

        const uint32_t st = smem_u32(sm + (i & 1) * STG);
        #pragma unroll
        for (int ks = 0; ks < 4; ks++) {
            uint32_t a[WM / 16][4], bh[WN / 16][4], bl[WN / 16][4];
            #pragma unroll
            for (int im = 0; im < WM / 16; im++) {
                int row = wm * WM + im * 16 + arow;
                ldsm4(a[im], st + swz(row, ks * 2 + akg));
            }
            #pragma unroll
            for (int j2 = 0; j2 < WN / 16; j2++) {
                int n = wn * WN + j2 * 16 + brow;
                uint32_t o = swz(n, ks * 2 + bkg);
                ldsm4(bh[j2], st + SA + o);
                ldsm4(bl[j2], st + SA + SB + o);
            }
            #pragma unroll
            for (int im = 0; im < WM / 16; im++)
                #pragma unroll
                for (int jn = 0; jn < WN / 8; jn++) {
                    float* c = acc + (im * (WN / 8) + jn) * 4;
                    const uint32_t* pbh = &bh[jn >> 1][(jn & 1) * 2];
                    const uint32_t* pbl = &bl[jn >> 1][(jn & 1) * 2];
                    mma16816(c, a[im], pbh);
                    mma16816(c, a[im], pbl);
                }
        }
    }
}

// epilogue iteration: f(row, col, val) over this thread's fragment elements
template<int BM, int BN, typename F>
__device__ __forceinline__ void epi(const float* acc, F&& f) {
    constexpr int WM = BM / 4, WN = BN / 2;
    const int lane = threadIdx.x & 31;
    const int warp = threadIdx.x >> 5;
    const int wm = warp >> 1, wn = warp & 1;
    const int g = lane >> 2, tg = lane & 3;
    #pragma unroll
    for (int im = 0; im < WM / 16; im++)
        #pragma unroll
        for (int jn = 0; jn < WN / 8; jn++)
            #pragma unroll
            for (int r = 0; r < 4; r++) {
                int row = wm * WM + im * 16 + g + ((r & 2) ? 8 : 0);
                int col = wn * WN + jn * 8 + tg * 2 + (r & 1);
                f(row, col, acc[(im * (WN / 8) + jn) * 4 + r]);
            }
}

// stage = 128*128 + 2*64*128 = 32 KB; 2 stages = 64 KB
#define SMEM_GEMM (2 * (128 * 128 + 2 * 64 * 128))

// ---------------------------------------------------------------------------
// QKV projection: BM=128, BN=64.  A = x (single), B = w (dual).
// z: 0 = k (scaled, dual out), 1 = q (scaled, single out), 2 = v -> Vt (dual,
// staged through smem for t-coalesced writes).
// ---------------------------------------------------------------------------
__global__ __launch_bounds__(256, 2) void proj_kernel() {
    const int n0 = blockIdx.x * 64;
    const int m0 = blockIdx.y * 128;
    const int z  = blockIdx.z;
    const f16* Wh = (z == 0) ? g_wkh : (z == 1) ? g_wqh : g_wvh;
    const f16* Wl = (z == 0) ? g_wkl : (z == 1) ? g_wql : g_wvl;

    float acc[32];
    tc_gemm<128, 64>(g_x + (size_t)m0 * E, E,
                     Wh + (size_t)n0 * E, Wl + (size_t)n0 * E, E, E, acc);

    if (z == 2) {
        extern __shared__ char sm[];
        float* smf = (float*)sm;              // 128 x 65 fp32 = 33.3 KB < 64 KB
        __syncthreads();
        epi<128, 64>(acc, [&](int row, int col, float v) {
            smf[row * 65 + col] = v;
        });
        __syncthreads();
        const int b = m0 >> 10, t_base = m0 & 1023;
        const int h = n0 >> 9,  ec_base = n0 & 511;
        const size_t vb = ((size_t)((b * H + h) * E + ec_base)) * T + t_base;
        const int tid = threadIdx.x;
        #pragma unroll
        for (int j = 0; j < 32; j++) {
            int idx = tid + j * 256;
            int ec_i = idx >> 7, t_i = idx & 127;
            float v = smf[t_i * 65 + ec_i];
            f16 hh, ll; f16split(v, hh, ll);
            size_t o = vb + (size_t)ec_i * T + t_i;
            g_vth[o] = hh; g_vtl[o] = ll;
        }
    } else if (z == 0) {
        epi<128, 64>(acc, [&](int row, int col, float v) {
            size_t o = (size_t)(m0 + row) * NPROJ + n0 + col;
            f16split(v * QK_SCALE, g_kh[o], g_kl[o]);
        });
    } else {
        epi<128, 64>(acc, [&](int row, int col, float v) {
            size_t o = (size_t)(m0 + row) * NPROJ + n0 + col;
            g_q[o] = __float2half(v * QK_SCALE);
        });
    }
}

// ---------------------------------------------------------------------------
// Scores: A = q (single), B = k (dual); lower-triangle tiles only,
// q index reversed for wave balance.
// ---------------------------------------------------------------------------
__global__ __launch_bounds__(256, 2) void scores_kernel() {
    const int k0 = blockIdx.x * 64;
    const int q0 = (int)(gridDim.y - 1 - blockIdx.y) * 128;
    if (k0 >= q0 + 128) return;
    const int bh = blockIdx.z;
    const int b = bh >> 3, h = bh & 7;
    const size_t base = (size_t)b * T * NPROJ + (size_t)h * E;

    float acc[32];
    tc_gemm<128, 64>(
        g_q + base + (size_t)q0 * NPROJ, NPROJ,
        g_kh + base + (size_t)k0 * NPROJ, g_kl + base + (size_t)k0 * NPROJ, NPROJ,
        E, acc);

    float* S = g_s + (size_t)bh * T * T;
    epi<128, 64>(acc, [&](int row, int col, float v) {
        S[(size_t)(q0 + row) * T + k0 + col] = v;
    });
}

// ---------------------------------------------------------------------------
// Softmax: float4 loads, shuffle reductions, single fp16 prob output.
// Writes only k < roundup128(trow+1).
// ---------------------------------------------------------------------------
__global__ void softmax_kernel() {
    const int row = blockIdx.x;
    const int trow = row & 1023;
    const int kend = (trow & ~127) + 128;
    const float4* __restrict__ S4 = (const float4*)(g_s + (size_t)row * T);
    f16* __restrict__ P = g_p + (size_t)row * T;
    const int tid = threadIdx.x;           // 256, each owns 4 consecutive
    const int lane = tid & 31, warp = tid >> 5;
    __shared__ float red[8];

    const int base = tid * 4;
    float4 s4 = S4[tid];
    float v[4] = { (base + 0 <= trow) ? s4.x : NEG_INF,
                   (base + 1 <= trow) ? s4.y : NEG_INF,
                   (base + 2 <= trow) ? s4.z : NEG_INF,
                   (base + 3 <= trow) ? s4.w : NEG_INF };

    float m = fmaxf(fmaxf(v[0], v[1]), fmaxf(v[2], v[3]));
    #pragma unroll
    for (int o = 16; o > 0; o >>= 1) m = fmaxf(m, __shfl_xor_sync(~0u, m, o));
    if (lane == 0) red[warp] = m;
    __syncthreads();
    m = red[0];
    #pragma unroll
    for (int w = 1; w < 8; w++) m = fmaxf(m, red[w]);
    __syncthreads();

    float sum = 0.f;
    #pragma unroll
    for (int i = 0; i < 4; i++) { v[i] = __expf(v[i] - m); sum += v[i]; }  // -inf -> 0
    #pragma unroll
    for (int o = 16; o > 0; o >>= 1) sum += __shfl_xor_sync(~0u, sum, o);
    if (lane == 0) red[warp] = sum;
    __syncthreads();
    sum = red[0];
    #pragma unroll
    for (int w = 1; w < 8; w++) sum += red[w];

    const float inv = 1.0f / sum;
    if (base < kend) {
        f16 p[4];
        #pragma unroll
        for (int i = 0; i < 4; i++) p[i] = __float2half(v[i] * inv);
        *(uint2*)(P + base) = *(const uint2*)p;
    }
}

// ---------------------------------------------------------------------------
// AV: A = P (single), B = Vt (dual); K truncated causally; q reversed.
// AO written single fp16.
// ---------------------------------------------------------------------------
__global__ __launch_bounds__(256, 2) void av_kernel() {
    const int n0 = blockIdx.x * 64;    // over E
    const int q0 = (int)(gridDim.y - 1 - blockIdx.y) * 128;
    const int bh = blockIdx.z;
    const int b = bh >> 3, h = bh & 7;
    const size_t pbase = (size_t)bh * T * T + (size_t)q0 * T;
    const size_t vbase = (size_t)bh * E * T + (size_t)n0 * T;

    float acc[32];
    tc_gemm<128, 64>(g_p + pbase, T,
                     g_vth + vbase, g_vtl + vbase, T,
                     q0 + 128, acc);

    epi<128, 64>(acc, [&](int row, int col, float v) {
        size_t o = (size_t)(b * T + q0 + row) * NPROJ + h * E + n0 + col;
        g_ao[o] = __float2half(v);
    });
}

// ---------------------------------------------------------------------------
// Unify: A = AO (single), B = wu (dual); out = AO @ wu^T + bu
// ---------------------------------------------------------------------------
__global__ __launch_bounds__(256, 2) void unify_kernel(const float* __restrict__ bu,
                                                       float* __restrict__ out) {
    const int n0 = blockIdx.x * 64;    // over E
    const int m0 = blockIdx.y * 128;

    float acc[32];
    tc_gemm<128, 64>(g_ao + (size_t)m0 * NPROJ, NPROJ,
                     g_wuh + (size_t)n0 * NPROJ, g_wul + (size_t)n0 * NPROJ, NPROJ,
                     NPROJ, acc);

    epi<128, 64>(acc, [&](int row, int col, float v) {
        out[(size_t)(m0 + row) * E + n0 + col] = v + bu[n0 + col];
    });
}

// ---------------------------------------------------------------------------
extern "C" void kernel_launch(void* const* d_in, const int* in_sizes, int n_in,
                              void* d_out, int out_size) {
    const float* x  = (const float*)d_in[0];
    const float* wk = (const float*)d_in[1];
    const float* wq = (const float*)d_in[2];
    const float* wv = (const float*)d_in[3];
    const float* wu = (const float*)d_in[4];
    const float* bu = (const float*)d_in[5];
    float* out = (float*)d_out;

    cudaFuncSetAttribute(proj_kernel,   cudaFuncAttributeMaxDynamicSharedMemorySize, SMEM_GEMM);
    cudaFuncSetAttribute(scores_kernel, cudaFuncAttributeMaxDynamicSharedMemorySize, SMEM_GEMM);
    cudaFuncSetAttribute(av_kernel,     cudaFuncAttributeMaxDynamicSharedMemorySize, SMEM_GEMM);
    cudaFuncSetAttribute(unify_kernel,  cudaFuncAttributeMaxDynamicSharedMemorySize, SMEM_GEMM);

    split_all<<<dim3(MTOT * E / 256, 5), 256>>>(x, wk, wq, wv, wu);

    proj_kernel  <<<dim3(NPROJ / 64, MTOT / 128, 3), 256, SMEM_GEMM>>>();
    scores_kernel<<<dim3(T / 64, T / 128, BH),        256, SMEM_GEMM>>>();
    softmax_kernel<<<BH * T, 256>>>();
    av_kernel    <<<dim3(E / 64, T / 128, BH),        256, SMEM_GEMM>>>();
    unify_kernel <<<dim3(E / 64, MTOT / 128),         256, SMEM_GEMM>>>(bu, out);
}

// round 11
// speedup vs baseline: 1.9243x; 1.2135x over previous
#include <cuda_runtime.h>
#include <cuda_fp16.h>
#include <cstdint>

// Problem shape (fixed)
#define Bb    4
#define T     1024
#define E     512
#define H     8
#define MTOT  (Bb*T)       // 4096
#define NPROJ (H*E)        // 4096
#define BH    (Bb*H)       // 32

#define NEG_INF (__int_as_float(0xff800000))
#define QK_SCALE 0.21022410381342864f   // 512^-0.25

typedef __half f16;

// ---------------- scratch (device globals; no allocs allowed) ----------------
__device__ __align__(16) f16 g_x[MTOT * E];                          // single
__device__ __align__(16) f16 g_wkh[NPROJ * E], g_wkl[NPROJ * E];     // dual (proj 2-mma)
__device__ __align__(16) f16 g_wqh[NPROJ * E], g_wql[NPROJ * E];
__device__ __align__(16) f16 g_wvh[NPROJ * E], g_wvl[NPROJ * E];
__device__ __align__(16) f16 g_wu[E * NPROJ];                        // single (unify 1-mma)
__device__ __align__(16) f16 g_q[MTOT * NPROJ];                      // single, pre-scaled
__device__ __align__(16) f16 g_k[MTOT * NPROJ];                      // single, pre-scaled
__device__ __align__(16) f16 g_vt[(size_t)BH * E * T];               // single (b,h,e,t)
__device__ float g_s[(size_t)BH * T * T];
__device__ __align__(16) f16 g_p[(size_t)BH * T * T];                // single probs
__device__ __align__(16) f16 g_ao[MTOT * NPROJ];                     // single

// ---------------------------------------------------------------------------
__device__ __forceinline__ uint32_t smem_u32(const void* p) {
    uint32_t a;
    asm("{ .reg .u64 t; cvta.to.shared.u64 t, %1; cvt.u32.u64 %0, t; }" : "=r"(a) : "l"(p));
    return a;
}
__device__ __forceinline__ void cp16(uint32_t dst, const void* src) {
    asm volatile("cp.async.cg.shared.global [%0], [%1], 16;" :: "r"(dst), "l"(src) : "memory");
}
#define CP_COMMIT()  asm volatile("cp.async.commit_group;" ::: "memory")
#define CP_WAIT(n)   asm volatile("cp.async.wait_group %0;" :: "n"(n) : "memory")

__device__ __forceinline__ void ldsm4(uint32_t* r, uint32_t addr) {
    asm volatile("ldmatrix.sync.aligned.m8n8.x4.shared.b16 {%0,%1,%2,%3}, [%4];"
                 : "=r"(r[0]), "=r"(r[1]), "=r"(r[2]), "=r"(r[3]) : "r"(addr));
}
__device__ __forceinline__ void mma16816(float* c, const uint32_t* a, const uint32_t* b) {
    asm volatile(
        "mma.sync.aligned.m16n8k16.row.col.f32.f16.f16.f32 "
        "{%0,%1,%2,%3}, {%4,%5,%6,%7}, {%8,%9}, {%0,%1,%2,%3};"
        : "+f"(c[0]), "+f"(c[1]), "+f"(c[2]), "+f"(c[3])
        : "r"(a[0]), "r"(a[1]), "r"(a[2]), "r"(a[3]), "r"(b[0]), "r"(b[1]));
}

__device__ __forceinline__ void f16split(float x, f16& h, f16& l) {
    h = __float2half(x);
    l = __float2half(x - __half2float(h));
}

// x, wu -> single fp16; wk/wq/wv -> fp16 hi/lo.  All are 2M elements.
__global__ void split_all(const float* __restrict__ x,  const float* __restrict__ wk,
                          const float* __restrict__ wq, const float* __restrict__ wv,
                          const float* __restrict__ wu) {
    const int i = blockIdx.x * 256 + threadIdx.x;
    if (blockIdx.y == 0) { g_x[i]  = __float2half(x[i]);  return; }
    if (blockIdx.y == 4) { g_wu[i] = __float2half(wu[i]); return; }
    const float* s; f16 *h, *l;
    switch (blockIdx.y) {
        case 1:  s = wk; h = g_wkh; l = g_wkl; break;
        case 2:  s = wq; h = g_wqh; l = g_wql; break;
        default: s = wv; h = g_wvh; l = g_wvl; break;
    }
    f16split(s[i], h[i], l[i]);
}

// SW128-style swizzle: 128B rows (64 f16 of K per row), kg = 16B group 0..7
__device__ __forceinline__ uint32_t swz(int row, int kg) {
    return row * 128 + ((kg ^ (row & 7)) << 4);
}

// ---------------------------------------------------------------------------
// GEMM core, 2-mma variant: C[BM,BN] = A[BM,K] x (Bh+Bl)[BN,K]^T.
// A single fp16, B split hi/lo.  256 threads, warp grid 4(m) x 2(n),
// warp tile 32x32, K-chunk 64, 2-stage cp.async, ONE __syncthreads per chunk.
// ---------------------------------------------------------------------------
template<int BM, int BN>
__device__ __forceinline__ void tc_gemm2(
    const f16* __restrict__ A, int lda,
    const f16* __restrict__ Bh, const f16* __restrict__ Bl, int ldb,
    int K, float* acc)
{
    constexpr int WM = BM / 4, WN = BN / 2;
    constexpr int SA = BM * 128;
    constexpr int SB = BN * 128;
    constexpr int STG = SA + 2 * SB;
    extern __shared__ char sm[];

    const int tid  = threadIdx.x;
    const int lane = tid & 31;
    const int warp = tid >> 5;
    const int wm = warp >> 1, wn = warp & 1;

    const int arow = ((lane >> 3) & 1) * 8 + (lane & 7);
    const int akg  = (lane >> 4) & 1;
    const int brow = ((lane >> 4) & 1) * 8 + (lane & 7);
    const int bkg  = (lane >> 3) & 1;

    #pragma unroll
    for (int i = 0; i < WM * WN / 32; i++) acc[i] = 0.f;

    const int nch = K >> 6;

    auto load_chunk = [&](int i) {
        const int k0 = i << 6;
        const uint32_t st = smem_u32(sm + (i & 1) * STG);
        #pragma unroll
        for (int j = 0; j < BM / 32; j++) {
            int idx = tid + j * 256;
            int r = idx >> 3, kg = idx & 7;
            cp16(st + swz(r, kg), A + (size_t)r * lda + k0 + kg * 8);
        }
        #pragma unroll
        for (int j = 0; j < BN / 32; j++) {
            int idx = tid + j * 256;
            int r = idx >> 3, kg = idx & 7;
            uint32_t o = swz(r, kg);
            cp16(st + SA + o,      Bh + (size_t)r * ldb + k0 + kg * 8);
            cp16(st + SA + SB + o, Bl + (size_t)r * ldb + k0 + kg * 8);
        }
        CP_COMMIT();
    };

    load_chunk(0);

    for (int i = 0; i < nch; i++) {
        CP_WAIT(0);
        __syncthreads();
        if (i + 1 < nch) load_chunk(i + 1);

        const uint32_t st = smem_u32(sm + (i & 1) * STG);
        #pragma unroll
        for (int ks = 0; ks < 4; ks++) {
            uint32_t a[WM / 16][4], bh[WN / 16][4], bl[WN / 16][4];
            #pragma unroll
            for (int im = 0; im < WM / 16; im++) {
                int row = wm * WM + im * 16 + arow;
                ldsm4(a[im], st + swz(row, ks * 2 + akg));
            }
            #pragma unroll
            for (int j2 = 0; j2 < WN / 16; j2++) {
                int n = wn * WN + j2 * 16 + brow;
                uint32_t o = swz(n, ks * 2 + bkg);
                ldsm4(bh[j2], st + SA + o);
                ldsm4(bl[j2], st + SA + SB + o);
            }
            #pragma unroll
            for (int im = 0; im < WM / 16; im++)
                #pragma unroll
                for (int jn = 0; jn < WN / 8; jn++) {
                    float* c = acc + (im * (WN / 8) + jn) * 4;
                    mma16816(c, a[im], &bh[jn >> 1][(jn & 1) * 2]);
                    mma16816(c, a[im], &bl[jn >> 1][(jn & 1) * 2]);
                }
        }
    }
}

// ---------------------------------------------------------------------------
// GEMM core, 1-mma variant: C[BM,BN] = A[BM,K] x B[BN,K]^T, both single fp16.
// Same schedule as tc_gemm2.
// ---------------------------------------------------------------------------
template<int BM, int BN>
__device__ __forceinline__ void tc_gemm1(
    const f16* __restrict__ A, int lda,
    const f16* __restrict__ B, int ldb,
    int K, float* acc)
{
    constexpr int WM = BM / 4, WN = BN / 2;
    constexpr int SA = BM * 128;
    constexpr int SB = BN * 128;
    constexpr int STG = SA + SB;
    extern __shared__ char sm[];

    const int tid  = threadIdx.x;
    const int lane = tid & 31;
    const int warp = tid >> 5;
    const int wm = warp >> 1, wn = warp & 1;

    const int arow = ((lane >> 3) & 1) * 8 + (lane & 7);
    const int akg  = (lane >> 4) & 1;
    const int brow = ((lane >> 4) & 1) * 8 + (lane & 7);
    const int bkg  = (lane >> 3) & 1;

    #pragma unroll
    for (int i = 0; i < WM * WN / 32; i++) acc[i] = 0.f;

    const int nch = K >> 6;

    auto load_chunk = [&](int i) {
        const int k0 = i << 6;
        const uint32_t st = smem_u32(sm + (i & 1) * STG);
        #pragma unroll
        for (int j = 0; j < BM / 32; j++) {
            int idx = tid + j * 256;
            int r = idx >> 3, kg = idx & 7;
            cp16(st + swz(r, kg), A + (size_t)r * lda + k0 + kg * 8);
        }
        #pragma unroll
        for (int j = 0; j < BN / 32; j++) {
            int idx = tid + j * 256;
            int r = idx >> 3, kg = idx & 7;
            cp16(st + SA + swz(r, kg), B + (size_t)r * ldb + k0 + kg * 8);
        }
        CP_COMMIT();
    };

    load_chunk(0);

    for (int i = 0; i < nch; i++) {
        CP_WAIT(0);
        __syncthreads();
        if (i + 1 < nch) load_chunk(i + 1);

        const uint32_t st = smem_u32(sm + (i & 1) * STG);
        #pragma unroll
        for (int ks = 0; ks < 4; ks++) {
            uint32_t a[WM / 16][4], b[WN / 16][4];
            #pragma unroll
            for (int im = 0; im < WM / 16; im++) {
                int row = wm * WM + im * 16 + arow;
                ldsm4(a[im], st + swz(row, ks * 2 + akg));
            }
            #pragma unroll
            for (int j2 = 0; j2 < WN / 16; j2++) {
                int n = wn * WN + j2 * 16 + brow;
                ldsm4(b[j2], st + SA + swz(n, ks * 2 + bkg));
            }
            #pragma unroll
            for (int im = 0; im < WM / 16; im++)
                #pragma unroll
                for (int jn = 0; jn < WN / 8; jn++)
                    mma16816(acc + (im * (WN / 8) + jn) * 4,
                             a[im], &b[jn >> 1][(jn & 1) * 2]);
        }
    }
}

// epilogue iteration: f(row, col, val) over this thread's fragment elements
template<int BM, int BN, typename F>
__device__ __forceinline__ void epi(const float* acc, F&& f) {
    constexpr int WM = BM / 4, WN = BN / 2;
    const int lane = threadIdx.x & 31;
    const int warp = threadIdx.x >> 5;
    const int wm = warp >> 1, wn = warp & 1;
    const int g = lane >> 2, tg = lane & 3;
    #pragma unroll
    for (int im = 0; im < WM / 16; im++)
        #pragma unroll
        for (int jn = 0; jn < WN / 8; jn++)
            #pragma unroll
            for (int r = 0; r < 4; r++) {
                int row = wm * WM + im * 16 + g + ((r & 2) ? 8 : 0);
                int col = wn * WN + jn * 8 + tg * 2 + (r & 1);
                f(row, col, acc[(im * (WN / 8) + jn) * 4 + r]);
            }
}

// 2-mma: stage 128*128 + 2*64*128 = 32 KB x2 = 64 KB
// 1-mma: stage 128*128 + 64*128 = 24 KB x2 = 48 KB
#define SMEM_GEMM2 (2 * (128 * 128 + 2 * 64 * 128))
#define SMEM_GEMM1 (2 * (128 * 128 + 64 * 128))

// ---------------------------------------------------------------------------
// QKV projection (2-mma, weights dual): BM=128, BN=64.
// z: 0 = k (scaled, single out), 1 = q (scaled, single out), 2 = v -> Vt
// (single, staged through smem for t-coalesced writes).
// ---------------------------------------------------------------------------
__global__ __launch_bounds__(256, 2) void proj_kernel() {
    const int n0 = blockIdx.x * 64;
    const int m0 = blockIdx.y * 128;
    const int z  = blockIdx.z;
    const f16* Wh = (z == 0) ? g_wkh : (z == 1) ? g_wqh : g_wvh;
    const f16* Wl = (z == 0) ? g_wkl : (z == 1) ? g_wql : g_wvl;

    float acc[32];
    tc_gemm2<128, 64>(g_x + (size_t)m0 * E, E,
                      Wh + (size_t)n0 * E, Wl + (size_t)n0 * E, E, E, acc);

    if (z == 2) {
        extern __shared__ char sm[];
        float* smf = (float*)sm;              // 128 x 65 fp32 = 33.3 KB < 64 KB
        __syncthreads();
        epi<128, 64>(acc, [&](int row, int col, float v) {
            smf[row * 65 + col] = v;
        });
        __syncthreads();
        const int b = m0 >> 10, t_base = m0 & 1023;
        const int h = n0 >> 9,  ec_base = n0 & 511;
        const size_t vb = ((size_t)((b * H + h) * E + ec_base)) * T + t_base;
        const int tid = threadIdx.x;
        #pragma unroll
        for (int j = 0; j < 32; j++) {
            int idx = tid + j * 256;
            int ec_i = idx >> 7, t_i = idx & 127;
            g_vt[vb + (size_t)ec_i * T + t_i] = __float2half(smf[t_i * 65 + ec_i]);
        }
    } else {
        f16* D = (z == 0) ? g_k : g_q;
        epi<128, 64>(acc, [&](int row, int col, float v) {
            D[(size_t)(m0 + row) * NPROJ + n0 + col] = __float2half(v * QK_SCALE);
        });
    }
}

// ---------------------------------------------------------------------------
// Scores (1-mma): A = q, B = k; lower-triangle tiles only, q reversed.
// ---------------------------------------------------------------------------
__global__ __launch_bounds__(256, 2) void scores_kernel() {
    const int k0 = blockIdx.x * 64;
    const int q0 = (int)(gridDim.y - 1 - blockIdx.y) * 128;
    if (k0 >= q0 + 128) return;
    const int bh = blockIdx.z;
    const int b = bh >> 3, h = bh & 7;
    const size_t base = (size_t)b * T * NPROJ + (size_t)h * E;

    float acc[32];
    tc_gemm1<128, 64>(g_q + base + (size_t)q0 * NPROJ, NPROJ,
                      g_k + base + (size_t)k0 * NPROJ, NPROJ, E, acc);

    float* S = g_s + (size_t)bh * T * T;
    epi<128, 64>(acc, [&](int row, int col, float v) {
        S[(size_t)(q0 + row) * T + k0 + col] = v;
    });
}

// ---------------------------------------------------------------------------
// Softmax: float4 loads, shuffle reductions, single fp16 prob output.
// Writes only k < roundup128(trow+1).
// ---------------------------------------------------------------------------
__global__ void softmax_kernel() {
    const int row = blockIdx.x;
    const int trow = row & 1023;
    const int kend = (trow & ~127) + 128;
    const float4* __restrict__ S4 = (const float4*)(g_s + (size_t)row * T);
    f16* __restrict__ P = g_p + (size_t)row * T;
    const int tid = threadIdx.x;
    const int lane = tid & 31, warp = tid >> 5;
    __shared__ float red[8];

    const int base = tid * 4;
    float4 s4 = S4[tid];
    float v[4] = { (base + 0 <= trow) ? s4.x : NEG_INF,
                   (base + 1 <= trow) ? s4.y : NEG_INF,
                   (base + 2 <= trow) ? s4.z : NEG_INF,
                   (base + 3 <= trow) ? s4.w : NEG_INF };

    float m = fmaxf(fmaxf(v[0], v[1]), fmaxf(v[2], v[3]));
    #pragma unroll
    for (int o = 16; o > 0; o >>= 1) m = fmaxf(m, __shfl_xor_sync(~0u, m, o));
    if (lane == 0) red[warp] = m;
    __syncthreads();
    m = red[0];
    #pragma unroll
    for (int w = 1; w < 8; w++) m = fmaxf(m, red[w]);
    __syncthreads();

    float sum = 0.f;
    #pragma unroll
    for (int i = 0; i < 4; i++) { v[i] = __expf(v[i] - m); sum += v[i]; }
    #pragma unroll
    for (int o = 16; o > 0; o >>= 1) sum += __shfl_xor_sync(~0u, sum, o);
    if (lane == 0) red[warp] = sum;
    __syncthreads();
    sum = red[0];
    #pragma unroll
    for (int w = 1; w < 8; w++) sum += red[w];

    const float inv = 1.0f / sum;
    if (base < kend) {
        f16 p[4];
        #pragma unroll
        for (int i = 0; i < 4; i++) p[i] = __float2half(v[i] * inv);
        *(uint2*)(P + base) = *(const uint2*)p;
    }
}

// ---------------------------------------------------------------------------
// AV (1-mma): A = P, B = Vt; K truncated causally; q reversed.
// ---------------------------------------------------------------------------
__global__ __launch_bounds__(256, 2) void av_kernel() {
    const int n0 = blockIdx.x * 64;
    const int q0 = (int)(gridDim.y - 1 - blockIdx.y) * 128;
    const int bh = blockIdx.z;
    const int b = bh >> 3, h = bh & 7;
    const size_t pbase = (size_t)bh * T * T + (size_t)q0 * T;
    const size_t vbase = (size_t)bh * E * T + (size_t)n0 * T;

    float acc[32];
    tc_gemm1<128, 64>(g_p + pbase, T, g_vt + vbase, T, q0 + 128, acc);

    epi<128, 64>(acc, [&](int row, int col, float v) {
        size_t o = (size_t)(b * T + q0 + row) * NPROJ + h * E + n0 + col;
        g_ao[o] = __float2half(v);
    });
}

// ---------------------------------------------------------------------------
// Unify (1-mma): A = AO, B = wu; out = AO @ wu^T + bu
// ---------------------------------------------------------------------------
__global__ __launch_bounds__(256, 2) void unify_kernel(const float* __restrict__ bu,
                                                       float* __restrict__ out) {
    const int n0 = blockIdx.x * 64;
    const int m0 = blockIdx.y * 128;

    float acc[32];
    tc_gemm1<128, 64>(g_ao + (size_t)m0 * NPROJ, NPROJ,
                      g_wu + (size_t)n0 * NPROJ, NPROJ, NPROJ, acc);

    epi<128, 64>(acc, [&](int row, int col, float v) {
        out[(size_t)(m0 + row) * E + n0 + col] = v + bu[n0 + col];
    });
}

// ---------------------------------------------------------------------------
extern "C" void kernel_launch(void* const* d_in, const int* in_sizes, int n_in,
                              void* d_out, int out_size) {
    const float* x  = (const float*)d_in[0];
    const float* wk = (const float*)d_in[1];
    const float* wq = (const float*)d_in[2];
    const float* wv = (const float*)d_in[3];
    const float* wu = (const float*)d_in[4];
    const float* bu = (const float*)d_in[5];
    float* out = (float*)d_out;

    cudaFuncSetAttribute(proj_kernel,   cudaFuncAttributeMaxDynamicSharedMemorySize, SMEM_GEMM2);
    cudaFuncSetAttribute(scores_kernel, cudaFuncAttributeMaxDynamicSharedMemorySize, SMEM_GEMM1);
    cudaFuncSetAttribute(av_kernel,     cudaFuncAttributeMaxDynamicSharedMemorySize, SMEM_GEMM1);
    cudaFuncSetAttribute(unify_kernel,  cudaFuncAttributeMaxDynamicSharedMemorySize, SMEM_GEMM1);

    split_all<<<dim3(MTOT * E / 256, 5), 256>>>(x, wk, wq, wv, wu);

    proj_kernel  <<<dim3(NPROJ / 64, MTOT / 128, 3), 256, SMEM_GEMM2>>>();
    scores_kernel<<<dim3(T / 64, T / 128, BH),        256, SMEM_GEMM1>>>();
    softmax_kernel<<<BH * T, 256>>>();
    av_kernel    <<<dim3(E / 64, T / 128, BH),        256, SMEM_GEMM1>>>();
    unify_kernel <<<dim3(E / 64, MTOT / 128),         256, SMEM_GEMM1>>>(bu, out);
}

// round 12
// speedup vs baseline: 2.3949x; 1.2445x over previous
#include <cuda_runtime.h>
#include <cuda_fp16.h>
#include <cstdint>

// Problem shape (fixed)
#define Bb    4
#define T     1024
#define E     512
#define H     8
#define MTOT  (Bb*T)       // 4096
#define NPROJ (H*E)        // 4096
#define BH    (Bb*H)       // 32

#define NEG_INF (__int_as_float(0xff800000))
#define QK_SCALE 0.21022410381342864f   // 512^-0.25

typedef __half f16;

// ---------------- scratch (device globals; no allocs allowed) ----------------
__device__ __align__(16) f16 g_x[MTOT * E];
__device__ __align__(16) f16 g_wk[NPROJ * E];
__device__ __align__(16) f16 g_wq[NPROJ * E];
__device__ __align__(16) f16 g_wv[NPROJ * E];
__device__ __align__(16) f16 g_wu[E * NPROJ];
__device__ __align__(16) f16 g_q[MTOT * NPROJ];        // pre-scaled
__device__ __align__(16) f16 g_k[MTOT * NPROJ];        // pre-scaled
__device__ __align__(16) f16 g_vt[(size_t)BH * E * T]; // (b,h,e,t)
__device__ float g_s[(size_t)BH * T * T];
__device__ __align__(16) f16 g_p[(size_t)BH * T * T];
__device__ __align__(16) f16 g_ao[MTOT * NPROJ];

// ---------------------------------------------------------------------------
__device__ __forceinline__ uint32_t smem_u32(const void* p) {
    uint32_t a;
    asm("{ .reg .u64 t; cvta.to.shared.u64 t, %1; cvt.u32.u64 %0, t; }" : "=r"(a) : "l"(p));
    return a;
}
__device__ __forceinline__ void cp16(uint32_t dst, const void* src) {
    asm volatile("cp.async.cg.shared.global [%0], [%1], 16;" :: "r"(dst), "l"(src) : "memory");
}
#define CP_COMMIT()  asm volatile("cp.async.commit_group;" ::: "memory")
#define CP_WAIT(n)   asm volatile("cp.async.wait_group %0;" :: "n"(n) : "memory")

__device__ __forceinline__ void ldsm4(uint32_t* r, uint32_t addr) {
    asm volatile("ldmatrix.sync.aligned.m8n8.x4.shared.b16 {%0,%1,%2,%3}, [%4];"
                 : "=r"(r[0]), "=r"(r[1]), "=r"(r[2]), "=r"(r[3]) : "r"(addr));
}
__device__ __forceinline__ void mma16816(float* c, const uint32_t* a, const uint32_t* b) {
    asm volatile(
        "mma.sync.aligned.m16n8k16.row.col.f32.f16.f16.f32 "
        "{%0,%1,%2,%3}, {%4,%5,%6,%7}, {%8,%9}, {%0,%1,%2,%3};"
        : "+f"(c[0]), "+f"(c[1]), "+f"(c[2]), "+f"(c[3])
        : "r"(a[0]), "r"(a[1]), "r"(a[2]), "r"(a[3]), "r"(b[0]), "r"(b[1]));
}

// all 5 inputs -> single fp16; each is 2M elements, float4-vectorized
__global__ void split_all(const float* __restrict__ x,  const float* __restrict__ wk,
                          const float* __restrict__ wq, const float* __restrict__ wv,
                          const float* __restrict__ wu) {
    const int i4 = blockIdx.x * 256 + threadIdx.x;    // float4 index
    const float* s; f16* d;
    switch (blockIdx.y) {
        case 0:  s = x;  d = g_x;  break;
        case 1:  s = wk; d = g_wk; break;
        case 2:  s = wq; d = g_wq; break;
        case 3:  s = wv; d = g_wv; break;
        default: s = wu; d = g_wu; break;
    }
    float4 v = ((const float4*)s)[i4];
    f16 o[4] = { __float2half(v.x), __float2half(v.y),
                 __float2half(v.z), __float2half(v.w) };
    *(uint2*)(d + i4 * 4) = *(const uint2*)o;
}

// SW128-style swizzle: 128B rows (64 f16 of K per row), kg = 16B group 0..7
__device__ __forceinline__ uint32_t swz(int row, int kg) {
    return row * 128 + ((kg ^ (row & 7)) << 4);
}

// ---------------------------------------------------------------------------
// GEMM core (1-mma): C[BM,BN] = A[BM,K] x B[BN,K]^T, both single fp16.
// 256 threads, warp grid 4(m) x 2(n), warp tile 32x32, K-chunk 64,
// 2-stage cp.async, ONE __syncthreads per chunk.
// ---------------------------------------------------------------------------
template<int BM, int BN>
__device__ __forceinline__ void tc_gemm1(
    const f16* __restrict__ A, int lda,
    const f16* __restrict__ B, int ldb,
    int K, float* acc)
{
    constexpr int WM = BM / 4, WN = BN / 2;
    constexpr int SA = BM * 128;
    constexpr int SB = BN * 128;
    constexpr int STG = SA + SB;
    extern __shared__ char sm[];

    const int tid  = threadIdx.x;
    const int lane = tid & 31;
    const int warp = tid >> 5;
    const int wm = warp >> 1, wn = warp & 1;

    const int arow = ((lane >> 3) & 1) * 8 + (lane & 7);
    const int akg  = (lane >> 4) & 1;
    const int brow = ((lane >> 4) & 1) * 8 + (lane & 7);
    const int bkg  = (lane >> 3) & 1;

    #pragma unroll
    for (int i = 0; i < WM * WN / 32; i++) acc[i] = 0.f;

    const int nch = K >> 6;

    auto load_chunk = [&](int i) {
        const int k0 = i << 6;
        const uint32_t st = smem_u32(sm + (i & 1) * STG);
        #pragma unroll
        for (int j = 0; j < BM / 32; j++) {
            int idx = tid + j * 256;
            int r = idx >> 3, kg = idx & 7;
            cp16(st + swz(r, kg), A + (size_t)r * lda + k0 + kg * 8);
        }
        #pragma unroll
        for (int j = 0; j < BN / 32; j++) {
            int idx = tid + j * 256;
            int r = idx >> 3, kg = idx & 7;
            cp16(st + SA + swz(r, kg), B + (size_t)r * ldb + k0 + kg * 8);
        }
        CP_COMMIT();
    };

    load_chunk(0);

    for (int i = 0; i < nch; i++) {
        CP_WAIT(0);
        __syncthreads();
        if (i + 1 < nch) load_chunk(i + 1);

        const uint32_t st = smem_u32(sm + (i & 1) * STG);
        #pragma unroll
        for (int ks = 0; ks < 4; ks++) {
            uint32_t a[WM / 16][4], b[WN / 16][4];
            #pragma unroll
            for (int im = 0; im < WM / 16; im++) {
                int row = wm * WM + im * 16 + arow;
                ldsm4(a[im], st + swz(row, ks * 2 + akg));
            }
            #pragma unroll
            for (int j2 = 0; j2 < WN / 16; j2++) {
                int n = wn * WN + j2 * 16 + brow;
                ldsm4(b[j2], st + SA + swz(n, ks * 2 + bkg));
            }
            #pragma unroll
            for (int im = 0; im < WM / 16; im++)
                #pragma unroll
                for (int jn = 0; jn < WN / 8; jn++)
                    mma16816(acc + (im * (WN / 8) + jn) * 4,
                             a[im], &b[jn >> 1][(jn & 1) * 2]);
        }
    }
}

// epilogue iteration: f(row, col, val) over this thread's fragment elements
template<int BM, int BN, typename F>
__device__ __forceinline__ void epi(const float* acc, F&& f) {
    constexpr int WM = BM / 4, WN = BN / 2;
    const int lane = threadIdx.x & 31;
    const int warp = threadIdx.x >> 5;
    const int wm = warp >> 1, wn = warp & 1;
    const int g = lane >> 2, tg = lane & 3;
    #pragma unroll
    for (int im = 0; im < WM / 16; im++)
        #pragma unroll
        for (int jn = 0; jn < WN / 8; jn++)
            #pragma unroll
            for (int r = 0; r < 4; r++) {
                int row = wm * WM + im * 16 + g + ((r & 2) ? 8 : 0);
                int col = wn * WN + jn * 8 + tg * 2 + (r & 1);
                f(row, col, acc[(im * (WN / 8) + jn) * 4 + r]);
            }
}

// stage = 128*128 + 64*128 = 24 KB; 2 stages = 48 KB
#define SMEM_GEMM (2 * (128 * 128 + 64 * 128))

// ---------------------------------------------------------------------------
// QKV projection (1-mma): BM=128, BN=64.
// z: 0 = k (scaled), 1 = q (scaled), 2 = v -> Vt (staged via smem, coalesced)
// ---------------------------------------------------------------------------
__global__ __launch_bounds__(256, 2) void proj_kernel() {
    const int n0 = blockIdx.x * 64;
    const int m0 = blockIdx.y * 128;
    const int z  = blockIdx.z;
    const f16* W = (z == 0) ? g_wk : (z == 1) ? g_wq : g_wv;

    float acc[32];
    tc_gemm1<128, 64>(g_x + (size_t)m0 * E, E, W + (size_t)n0 * E, E, E, acc);

    if (z == 2) {
        extern __shared__ char sm[];
        float* smf = (float*)sm;              // 128 x 65 fp32 = 33.3 KB < 48 KB
        __syncthreads();
        epi<128, 64>(acc, [&](int row, int col, float v) {
            smf[row * 65 + col] = v;
        });
        __syncthreads();
        const int b = m0 >> 10, t_base = m0 & 1023;
        const int h = n0 >> 9,  ec_base = n0 & 511;
        const size_t vb = ((size_t)((b * H + h) * E + ec_base)) * T + t_base;
        const int tid = threadIdx.x;
        #pragma unroll
        for (int j = 0; j < 32; j++) {
            int idx = tid + j * 256;
            int ec_i = idx >> 7, t_i = idx & 127;
            g_vt[vb + (size_t)ec_i * T + t_i] = __float2half(smf[t_i * 65 + ec_i]);
        }
    } else {
        f16* D = (z == 0) ? g_k : g_q;
        epi<128, 64>(acc, [&](int row, int col, float v) {
            D[(size_t)(m0 + row) * NPROJ + n0 + col] = __float2half(v * QK_SCALE);
        });
    }
}

// ---------------------------------------------------------------------------
// Scores (1-mma): A = q, B = k; lower-triangle tiles only, q reversed.
// ---------------------------------------------------------------------------
__global__ __launch_bounds__(256, 2) void scores_kernel() {
    const int k0 = blockIdx.x * 64;
    const int q0 = (int)(gridDim.y - 1 - blockIdx.y) * 128;
    if (k0 >= q0 + 128) return;
    const int bh = blockIdx.z;
    const int b = bh >> 3, h = bh & 7;
    const size_t base = (size_t)b * T * NPROJ + (size_t)h * E;

    float acc[32];
    tc_gemm1<128, 64>(g_q + base + (size_t)q0 * NPROJ, NPROJ,
                      g_k + base + (size_t)k0 * NPROJ, NPROJ, E, acc);

    float* S = g_s + (size_t)bh * T * T;
    epi<128, 64>(acc, [&](int row, int col, float v) {
        S[(size_t)(q0 + row) * T + k0 + col] = v;
    });
}

// ---------------------------------------------------------------------------
// Softmax: float4 loads, shuffle reductions, single fp16 prob output.
// Writes only k < roundup128(trow+1).
// ---------------------------------------------------------------------------
__global__ void softmax_kernel() {
    const int row = blockIdx.x;
    const int trow = row & 1023;
    const int kend = (trow & ~127) + 128;
    const float4* __restrict__ S4 = (const float4*)(g_s + (size_t)row * T);
    f16* __restrict__ P = g_p + (size_t)row * T;
    const int tid = threadIdx.x;
    const int lane = tid & 31, warp = tid >> 5;
    __shared__ float red[8];

    const int base = tid * 4;
    float4 s4 = S4[tid];
    float v[4] = { (base + 0 <= trow) ? s4.x : NEG_INF,
                   (base + 1 <= trow) ? s4.y : NEG_INF,
                   (base + 2 <= trow) ? s4.z : NEG_INF,
                   (base + 3 <= trow) ? s4.w : NEG_INF };

    float m = fmaxf(fmaxf(v[0], v[1]), fmaxf(v[2], v[3]));
    #pragma unroll
    for (int o = 16; o > 0; o >>= 1) m = fmaxf(m, __shfl_xor_sync(~0u, m, o));
    if (lane == 0) red[warp] = m;
    __syncthreads();
    m = red[0];
    #pragma unroll
    for (int w = 1; w < 8; w++) m = fmaxf(m, red[w]);
    __syncthreads();

    float sum = 0.f;
    #pragma unroll
    for (int i = 0; i < 4; i++) { v[i] = __expf(v[i] - m); sum += v[i]; }
    #pragma unroll
    for (int o = 16; o > 0; o >>= 1) sum += __shfl_xor_sync(~0u, sum, o);
    if (lane == 0) red[warp] = sum;
    __syncthreads();
    sum = red[0];
    #pragma unroll
    for (int w = 1; w < 8; w++) sum += red[w];

    const float inv = 1.0f / sum;
    if (base < kend) {
        f16 p[4];
        #pragma unroll
        for (int i = 0; i < 4; i++) p[i] = __float2half(v[i] * inv);
        *(uint2*)(P + base) = *(const uint2*)p;
    }
}

// ---------------------------------------------------------------------------
// AV (1-mma): A = P, B = Vt; K truncated causally; q reversed.
// ---------------------------------------------------------------------------
__global__ __launch_bounds__(256, 2) void av_kernel() {
    const int n0 = blockIdx.x * 64;
    const int q0 = (int)(gridDim.y - 1 - blockIdx.y) * 128;
    const int bh = blockIdx.z;
    const int b = bh >> 3, h = bh & 7;
    const size_t pbase = (size_t)bh * T * T + (size_t)q0 * T;
    const size_t vbase = (size_t)bh * E * T + (size_t)n0 * T;

    float acc[32];
    tc_gemm1<128, 64>(g_p + pbase, T, g_vt + vbase, T, q0 + 128, acc);

    epi<128, 64>(acc, [&](int row, int col, float v) {
        size_t o = (size_t)(b * T + q0 + row) * NPROJ + h * E + n0 + col;
        g_ao[o] = __float2half(v);
    });
}

// ---------------------------------------------------------------------------
// Unify (1-mma): A = AO, B = wu; out = AO @ wu^T + bu
// ---------------------------------------------------------------------------
__global__ __launch_bounds__(256, 2) void unify_kernel(const float* __restrict__ bu,
                                                       float* __restrict__ out) {
    const int n0 = blockIdx.x * 64;
    const int m0 = blockIdx.y * 128;

    float acc[32];
    tc_gemm1<128, 64>(g_ao + (size_t)m0 * NPROJ, NPROJ,
                      g_wu + (size_t)n0 * NPROJ, NPROJ, NPROJ, acc);

    epi<128, 64>(acc, [&](int row, int col, float v) {
        out[(size_t)(m0 + row) * E + n0 + col] = v + bu[n0 + col];
    });
}

// ---------------------------------------------------------------------------
extern "C" void kernel_launch(void* const* d_in, const int* in_sizes, int n_in,
                              void* d_out, int out_size) {
    const float* x  = (const float*)d_in[0];
    const float* wk = (const float*)d_in[1];
    const float* wq = (const float*)d_in[2];
    const float* wv = (const float*)d_in[3];
    const float* wu = (const float*)d_in[4];
    const float* bu = (const float*)d_in[5];
    float* out = (float*)d_out;

    cudaFuncSetAttribute(proj_kernel,   cudaFuncAttributeMaxDynamicSharedMemorySize, SMEM_GEMM);
    cudaFuncSetAttribute(scores_kernel, cudaFuncAttributeMaxDynamicSharedMemorySize, SMEM_GEMM);
    cudaFuncSetAttribute(av_kernel,     cudaFuncAttributeMaxDynamicSharedMemorySize, SMEM_GEMM);
    cudaFuncSetAttribute(unify_kernel,  cudaFuncAttributeMaxDynamicSharedMemorySize, SMEM_GEMM);

    split_all<<<dim3(MTOT * E / 1024, 5), 256>>>(x, wk, wq, wv, wu);

    proj_kernel  <<<dim3(NPROJ / 64, MTOT / 128, 3), 256, SMEM_GEMM>>>();
    scores_kernel<<<dim3(T / 64, T / 128, BH),        256, SMEM_GEMM>>>();
    softmax_kernel<<<BH * T, 256>>>();
    av_kernel    <<<dim3(E / 64, T / 128, BH),        256, SMEM_GEMM>>>();
    unify_kernel <<<dim3(E / 64, MTOT / 128),         256, SMEM_GEMM>>>(bu, out);
}

// round 13
// speedup vs baseline: 2.6085x; 1.0892x over previous
#include <cuda_runtime.h>
#include <cuda_fp16.h>
#include <cstdint>

// Problem shape (fixed)
#define Bb    4
#define T     1024
#define E     512
#define H     8
#define MTOT  (Bb*T)       // 4096
#define NPROJ (H*E)        // 4096
#define BH    (Bb*H)       // 32

#define NEG_INF (__int_as_float(0xff800000))
#define QK_SCALE 0.21022410381342864f   // 512^-0.25

typedef __half f16;

// ---------------- scratch (device globals; no allocs allowed) ----------------
__device__ __align__(16) f16 g_x[MTOT * E];
__device__ __align__(16) f16 g_wk[NPROJ * E];
__device__ __align__(16) f16 g_wq[NPROJ * E];
__device__ __align__(16) f16 g_wv[NPROJ * E];
__device__ __align__(16) f16 g_wu[E * NPROJ];
__device__ __align__(16) f16 g_q[MTOT * NPROJ];        // pre-scaled
__device__ __align__(16) f16 g_k[MTOT * NPROJ];        // pre-scaled
__device__ __align__(16) f16 g_vt[(size_t)BH * E * T]; // (b,h,e,t)
__device__ __align__(16) f16 g_s[(size_t)BH * T * T];  // fp16 scores
__device__ __align__(16) f16 g_p[(size_t)BH * T * T];
__device__ __align__(16) f16 g_ao[MTOT * NPROJ];

// ---------------------------------------------------------------------------
__device__ __forceinline__ uint32_t smem_u32(const void* p) {
    uint32_t a;
    asm("{ .reg .u64 t; cvta.to.shared.u64 t, %1; cvt.u32.u64 %0, t; }" : "=r"(a) : "l"(p));
    return a;
}
__device__ __forceinline__ void cp16(uint32_t dst, const void* src) {
    asm volatile("cp.async.cg.shared.global [%0], [%1], 16;" :: "r"(dst), "l"(src) : "memory");
}
#define CP_COMMIT()  asm volatile("cp.async.commit_group;" ::: "memory")
#define CP_WAIT(n)   asm volatile("cp.async.wait_group %0;" :: "n"(n) : "memory")

__device__ __forceinline__ void ldsm4(uint32_t* r, uint32_t addr) {
    asm volatile("ldmatrix.sync.aligned.m8n8.x4.shared.b16 {%0,%1,%2,%3}, [%4];"
                 : "=r"(r[0]), "=r"(r[1]), "=r"(r[2]), "=r"(r[3]) : "r"(addr));
}
__device__ __forceinline__ void mma16816(float* c, const uint32_t* a, const uint32_t* b) {
    asm volatile(
        "mma.sync.aligned.m16n8k16.row.col.f32.f16.f16.f32 "
        "{%0,%1,%2,%3}, {%4,%5,%6,%7}, {%8,%9}, {%0,%1,%2,%3};"
        : "+f"(c[0]), "+f"(c[1]), "+f"(c[2]), "+f"(c[3])
        : "r"(a[0]), "r"(a[1]), "r"(a[2]), "r"(a[3]), "r"(b[0]), "r"(b[1]));
}

// all 5 inputs -> single fp16; each is 2M elements, float4-vectorized
__global__ void split_all(const float* __restrict__ x,  const float* __restrict__ wk,
                          const float* __restrict__ wq, const float* __restrict__ wv,
                          const float* __restrict__ wu) {
    const int i4 = blockIdx.x * 256 + threadIdx.x;    // float4 index
    const float* s; f16* d;
    switch (blockIdx.y) {
        case 0:  s = x;  d = g_x;  break;
        case 1:  s = wk; d = g_wk; break;
        case 2:  s = wq; d = g_wq; break;
        case 3:  s = wv; d = g_wv; break;
        default: s = wu; d = g_wu; break;
    }
    float4 v = ((const float4*)s)[i4];
    f16 o[4] = { __float2half(v.x), __float2half(v.y),
                 __float2half(v.z), __float2half(v.w) };
    *(uint2*)(d + i4 * 4) = *(const uint2*)o;
}

// swizzle for 256B rows (128 f16 of K per row); kg = 16B group 0..15.
// XOR with (row & 7) keeps ldmatrix (8 rows, same kg) conflict-free.
__device__ __forceinline__ uint32_t swz(int row, int kg) {
    return row * 256 + ((kg ^ (row & 7)) << 4);
}

// ---------------------------------------------------------------------------
// GEMM core (1-mma): C[BM,BN] = A[BM,K] x B[BN,K]^T, both single fp16.
// 256 threads, warp grid 4(m) x 2(n), warp tile 32x32, K-chunk 128,
// 2-stage cp.async, ONE __syncthreads per chunk.
// ---------------------------------------------------------------------------
template<int BM, int BN>
__device__ __forceinline__ void tc_gemm1(
    const f16* __restrict__ A, int lda,
    const f16* __restrict__ B, int ldb,
    int K, float* acc)
{
    constexpr int WM = BM / 4, WN = BN / 2;
    constexpr int SA = BM * 256;
    constexpr int SB = BN * 256;
    constexpr int STG = SA + SB;
    extern __shared__ char sm[];

    const int tid  = threadIdx.x;
    const int lane = tid & 31;
    const int warp = tid >> 5;
    const int wm = warp >> 1, wn = warp & 1;

    const int arow = ((lane >> 3) & 1) * 8 + (lane & 7);
    const int akg  = (lane >> 4) & 1;
    const int brow = ((lane >> 4) & 1) * 8 + (lane & 7);
    const int bkg  = (lane >> 3) & 1;

    #pragma unroll
    for (int i = 0; i < WM * WN / 32; i++) acc[i] = 0.f;

    const int nch = K >> 7;

    auto load_chunk = [&](int i) {
        const int k0 = i << 7;
        const uint32_t st = smem_u32(sm + (i & 1) * STG);
        #pragma unroll
        for (int j = 0; j < BM / 16; j++) {        // BM*16 16B-chunks / 256 thr
            int idx = tid + j * 256;
            int r = idx >> 4, kg = idx & 15;
            cp16(st + swz(r, kg), A + (size_t)r * lda + k0 + kg * 8);
        }
        #pragma unroll
        for (int j = 0; j < BN / 16; j++) {
            int idx = tid + j * 256;
            int r = idx >> 4, kg = idx & 15;
            cp16(st + SA + swz(r, kg), B + (size_t)r * ldb + k0 + kg * 8);
        }
        CP_COMMIT();
    };

    load_chunk(0);

    for (int i = 0; i < nch; i++) {
        CP_WAIT(0);
        __syncthreads();
        if (i + 1 < nch) load_chunk(i + 1);

        const uint32_t st = smem_u32(sm + (i & 1) * STG);
        #pragma unroll
        for (int ks = 0; ks < 8; ks++) {
            uint32_t a[WM / 16][4], b[WN / 16][4];
            #pragma unroll
            for (int im = 0; im < WM / 16; im++) {
                int row = wm * WM + im * 16 + arow;
                ldsm4(a[im], st + swz(row, ks * 2 + akg));
            }
            #pragma unroll
            for (int j2 = 0; j2 < WN / 16; j2++) {
                int n = wn * WN + j2 * 16 + brow;
                ldsm4(b[j2], st + SA + swz(n, ks * 2 + bkg));
            }
            #pragma unroll
            for (int im = 0; im < WM / 16; im++)
                #pragma unroll
                for (int jn = 0; jn < WN / 8; jn++)
                    mma16816(acc + (im * (WN / 8) + jn) * 4,
                             a[im], &b[jn >> 1][(jn & 1) * 2]);
        }
    }
}

// epilogue iteration: f(row, col, val) over this thread's fragment elements
template<int BM, int BN, typename F>
__device__ __forceinline__ void epi(const float* acc, F&& f) {
    constexpr int WM = BM / 4, WN = BN / 2;
    const int lane = threadIdx.x & 31;
    const int warp = threadIdx.x >> 5;
    const int wm = warp >> 1, wn = warp & 1;
    const int g = lane >> 2, tg = lane & 3;
    #pragma unroll
    for (int im = 0; im < WM / 16; im++)
        #pragma unroll
        for (int jn = 0; jn < WN / 8; jn++)
            #pragma unroll
            for (int r = 0; r < 4; r++) {
                int row = wm * WM + im * 16 + g + ((r & 2) ? 8 : 0);
                int col = wn * WN + jn * 8 + tg * 2 + (r & 1);
                f(row, col, acc[(im * (WN / 8) + jn) * 4 + r]);
            }
}

// stage = 128*256 + 64*256 = 48 KB; 2 stages = 96 KB (192 KB/SM at 2 CTA)
#define SMEM_GEMM (2 * (128 * 256 + 64 * 256))

// ---------------------------------------------------------------------------
// QKV projection (1-mma): BM=128, BN=64.
// z: 0 = k (scaled), 1 = q (scaled), 2 = v -> Vt (staged via smem, coalesced)
// ---------------------------------------------------------------------------
__global__ __launch_bounds__(256, 2) void proj_kernel() {
    const int n0 = blockIdx.x * 64;
    const int m0 = blockIdx.y * 128;
    const int z  = blockIdx.z;
    const f16* W = (z == 0) ? g_wk : (z == 1) ? g_wq : g_wv;

    float acc[32];
    tc_gemm1<128, 64>(g_x + (size_t)m0 * E, E, W + (size_t)n0 * E, E, E, acc);

    if (z == 2) {
        extern __shared__ char sm[];
        float* smf = (float*)sm;              // 128 x 65 fp32 = 33.3 KB < 96 KB
        __syncthreads();
        epi<128, 64>(acc, [&](int row, int col, float v) {
            smf[row * 65 + col] = v;
        });
        __syncthreads();
        const int b = m0 >> 10, t_base = m0 & 1023;
        const int h = n0 >> 9,  ec_base = n0 & 511;
        const size_t vb = ((size_t)((b * H + h) * E + ec_base)) * T + t_base;
        const int tid = threadIdx.x;
        #pragma unroll
        for (int j = 0; j < 32; j++) {
            int idx = tid + j * 256;
            int ec_i = idx >> 7, t_i = idx & 127;
            g_vt[vb + (size_t)ec_i * T + t_i] = __float2half(smf[t_i * 65 + ec_i]);
        }
    } else {
        f16* D = (z == 0) ? g_k : g_q;
        epi<128, 64>(acc, [&](int row, int col, float v) {
            D[(size_t)(m0 + row) * NPROJ + n0 + col] = __float2half(v * QK_SCALE);
        });
    }
}

// ---------------------------------------------------------------------------
// Scores (1-mma): A = q, B = k; lower-triangle tiles only, q reversed.
// S stored fp16.
// ---------------------------------------------------------------------------
__global__ __launch_bounds__(256, 2) void scores_kernel() {
    const int k0 = blockIdx.x * 64;
    const int q0 = (int)(gridDim.y - 1 - blockIdx.y) * 128;
    if (k0 >= q0 + 128) return;
    const int bh = blockIdx.z;
    const int b = bh >> 3, h = bh & 7;
    const size_t base = (size_t)b * T * NPROJ + (size_t)h * E;

    float acc[32];
    tc_gemm1<128, 64>(g_q + base + (size_t)q0 * NPROJ, NPROJ,
                      g_k + base + (size_t)k0 * NPROJ, NPROJ, E, acc);

    f16* S = g_s + (size_t)bh * T * T;
    epi<128, 64>(acc, [&](int row, int col, float v) {
        S[(size_t)(q0 + row) * T + k0 + col] = __float2half(v);
    });
}

// ---------------------------------------------------------------------------
// Softmax: fp16 score loads (uint2 = 4 halves), shuffle reductions,
// single fp16 prob output.  Writes only k < roundup128(trow+1).
// ---------------------------------------------------------------------------
__global__ void softmax_kernel() {
    const int row = blockIdx.x;
    const int trow = row & 1023;
    const int kend = (trow & ~127) + 128;
    const f16* __restrict__ S = g_s + (size_t)row * T;
    f16* __restrict__ P = g_p + (size_t)row * T;
    const int tid = threadIdx.x;
    const int lane = tid & 31, warp = tid >> 5;
    __shared__ float red[8];

    const int base = tid * 4;
    f16 s4[4];
    *(uint2*)s4 = *(const uint2*)(S + base);
    float v[4];
    #pragma unroll
    for (int i = 0; i < 4; i++)
        v[i] = (base + i <= trow) ? __half2float(s4[i]) : NEG_INF;

    float m = fmaxf(fmaxf(v[0], v[1]), fmaxf(v[2], v[3]));
    #pragma unroll
    for (int o = 16; o > 0; o >>= 1) m = fmaxf(m, __shfl_xor_sync(~0u, m, o));
    if (lane == 0) red[warp] = m;
    __syncthreads();
    m = red[0];
    #pragma unroll
    for (int w = 1; w < 8; w++) m = fmaxf(m, red[w]);
    __syncthreads();

    float sum = 0.f;
    #pragma unroll
    for (int i = 0; i < 4; i++) { v[i] = __expf(v[i] - m); sum += v[i]; }
    #pragma unroll
    for (int o = 16; o > 0; o >>= 1) sum += __shfl_xor_sync(~0u, sum, o);
    if (lane == 0) red[warp] = sum;
    __syncthreads();
    sum = red[0];
    #pragma unroll
    for (int w = 1; w < 8; w++) sum += red[w];

    const float inv = 1.0f / sum;
    if (base < kend) {
        f16 p[4];
        #pragma unroll
        for (int i = 0; i < 4; i++) p[i] = __float2half(v[i] * inv);
        *(uint2*)(P + base) = *(const uint2*)p;
    }
}

// ---------------------------------------------------------------------------
// AV (1-mma): A = P, B = Vt; K truncated causally; q reversed.
// ---------------------------------------------------------------------------
__global__ __launch_bounds__(256, 2) void av_kernel() {
    const int n0 = blockIdx.x * 64;
    const int q0 = (int)(gridDim.y - 1 - blockIdx.y) * 128;
    const int bh = blockIdx.z;
    const int b = bh >> 3, h = bh & 7;
    const size_t pbase = (size_t)bh * T * T + (size_t)q0 * T;
    const size_t vbase = (size_t)bh * E * T + (size_t)n0 * T;

    float acc[32];
    tc_gemm1<128, 64>(g_p + pbase, T, g_vt + vbase, T, q0 + 128, acc);

    epi<128, 64>(acc, [&](int row, int col, float v) {
        size_t o = (size_t)(b * T + q0 + row) * NPROJ + h * E + n0 + col;
        g_ao[o] = __float2half(v);
    });
}

// ---------------------------------------------------------------------------
// Unify (1-mma): A = AO, B = wu; out = AO @ wu^T + bu
// ---------------------------------------------------------------------------
__global__ __launch_bounds__(256, 2) void unify_kernel(const float* __restrict__ bu,
                                                       float* __restrict__ out) {
    const int n0 = blockIdx.x * 64;
    const int m0 = blockIdx.y * 128;

    float acc[32];
    tc_gemm1<128, 64>(g_ao + (size_t)m0 * NPROJ, NPROJ,
                      g_wu + (size_t)n0 * NPROJ, NPROJ, NPROJ, acc);

    epi<128, 64>(acc, [&](int row, int col, float v) {
        out[(size_t)(m0 + row) * E + n0 + col] = v + bu[n0 + col];
    });
}

// ---------------------------------------------------------------------------
extern "C" void kernel_launch(void* const* d_in, const int* in_sizes, int n_in,
                              void* d_out, int out_size) {
    const float* x  = (const float*)d_in[0];
    const float* wk = (const float*)d_in[1];
    const float* wq = (const float*)d_in[2];
    const float* wv = (const float*)d_in[3];
    const float* wu = (const float*)d_in[4];
    const float* bu = (const float*)d_in[5];
    float* out = (float*)d_out;

    cudaFuncSetAttribute(proj_kernel,   cudaFuncAttributeMaxDynamicSharedMemorySize, SMEM_GEMM);
    cudaFuncSetAttribute(scores_kernel, cudaFuncAttributeMaxDynamicSharedMemorySize, SMEM_GEMM);
    cudaFuncSetAttribute(av_kernel,     cudaFuncAttributeMaxDynamicSharedMemorySize, SMEM_GEMM);
    cudaFuncSetAttribute(unify_kernel,  cudaFuncAttributeMaxDynamicSharedMemorySize, SMEM_GEMM);

    split_all<<<dim3(MTOT * E / 1024, 5), 256>>>(x, wk, wq, wv, wu);

    proj_kernel  <<<dim3(NPROJ / 64, MTOT / 128, 3), 256, SMEM_GEMM>>>();
    scores_kernel<<<dim3(T / 64, T / 128, BH),        256, SMEM_GEMM>>>();
    softmax_kernel<<<BH * T, 256>>>();
    av_kernel    <<<dim3(E / 64, T / 128, BH),        256, SMEM_GEMM>>>();
    unify_kernel <<<dim3(E / 64, MTOT / 128),         256, SMEM_GEMM>>>(bu, out);
}

// round 14
// speedup vs baseline: 2.7791x; 1.0654x over previous
#include <cuda_runtime.h>
#include <cuda_fp16.h>
#include <cstdint>

// Problem shape (fixed)
#define Bb    4
#define T     1024
#define E     512
#define H     8
#define MTOT  (Bb*T)       // 4096
#define NPROJ (H*E)        // 4096
#define BH    (Bb*H)       // 32

#define NEG_INF (__int_as_float(0xff800000))
#define QK_SCALE 0.21022410381342864f   // 512^-0.25

typedef __half f16;

// ---------------- scratch (device globals; no allocs allowed) ----------------
__device__ __align__(16) f16 g_x[MTOT * E];
__device__ __align__(16) f16 g_wk[NPROJ * E];
__device__ __align__(16) f16 g_wq[NPROJ * E];
__device__ __align__(16) f16 g_wv[NPROJ * E];
__device__ __align__(16) f16 g_wu[E * NPROJ];
__device__ __align__(16) f16 g_q[MTOT * NPROJ];        // pre-scaled
__device__ __align__(16) f16 g_k[MTOT * NPROJ];        // pre-scaled
__device__ __align__(16) f16 g_vt[(size_t)BH * E * T]; // (b,h,e,t)
__device__ __align__(16) f16 g_s[(size_t)BH * T * T];  // fp16 scores
__device__ __align__(16) f16 g_p[(size_t)BH * T * T];
__device__ __align__(16) f16 g_ao[MTOT * NPROJ];

// ---------------------------------------------------------------------------
__device__ __forceinline__ uint32_t smem_u32(const void* p) {
    uint32_t a;
    asm("{ .reg .u64 t; cvta.to.shared.u64 t, %1; cvt.u32.u64 %0, t; }" : "=r"(a) : "l"(p));
    return a;
}
__device__ __forceinline__ void cp16(uint32_t dst, const void* src) {
    asm volatile("cp.async.cg.shared.global [%0], [%1], 16;" :: "r"(dst), "l"(src) : "memory");
}
#define CP_COMMIT()  asm volatile("cp.async.commit_group;" ::: "memory")
#define CP_WAIT(n)   asm volatile("cp.async.wait_group %0;" :: "n"(n) : "memory")

__device__ __forceinline__ void ldsm4(uint32_t* r, uint32_t addr) {
    asm volatile("ldmatrix.sync.aligned.m8n8.x4.shared.b16 {%0,%1,%2,%3}, [%4];"
                 : "=r"(r[0]), "=r"(r[1]), "=r"(r[2]), "=r"(r[3]) : "r"(addr));
}
__device__ __forceinline__ void mma16816(float* c, const uint32_t* a, const uint32_t* b) {
    asm volatile(
        "mma.sync.aligned.m16n8k16.row.col.f32.f16.f16.f32 "
        "{%0,%1,%2,%3}, {%4,%5,%6,%7}, {%8,%9}, {%0,%1,%2,%3};"
        : "+f"(c[0]), "+f"(c[1]), "+f"(c[2]), "+f"(c[3])
        : "r"(a[0]), "r"(a[1]), "r"(a[2]), "r"(a[3]), "r"(b[0]), "r"(b[1]));
}

// all 5 inputs -> single fp16; each is 2M elements, float4-vectorized
__global__ void split_all(const float* __restrict__ x,  const float* __restrict__ wk,
                          const float* __restrict__ wq, const float* __restrict__ wv,
                          const float* __restrict__ wu) {
    const int i4 = blockIdx.x * 256 + threadIdx.x;    // float4 index
    const float* s; f16* d;
    switch (blockIdx.y) {
        case 0:  s = x;  d = g_x;  break;
        case 1:  s = wk; d = g_wk; break;
        case 2:  s = wq; d = g_wq; break;
        case 3:  s = wv; d = g_wv; break;
        default: s = wu; d = g_wu; break;
    }
    float4 v = ((const float4*)s)[i4];
    f16 o[4] = { __float2half(v.x), __float2half(v.y),
                 __float2half(v.z), __float2half(v.w) };
    *(uint2*)(d + i4 * 4) = *(const uint2*)o;
}

// swizzle for ROWB-byte rows; kg = 16B group.  XOR with (row & 7) keeps
// ldmatrix (8 rows, same kg) conflict-free for both ROWB=128 and 256.
template<int ROWB>
__device__ __forceinline__ uint32_t swz(int row, int kg) {
    return row * ROWB + ((kg ^ (row & 7)) << 4);
}

// ---------------------------------------------------------------------------
// GEMM core (1-mma): C[BM,BN] = A[BM,K] x B[BN,K]^T, both single fp16.
// 256 threads, warp grid 4(m) x 2(n), warp tile BM/4 x BN/2, K-chunk CK,
// 2-stage cp.async, ONE __syncthreads per chunk.
// ---------------------------------------------------------------------------
template<int BM, int BN, int CK>
__device__ __forceinline__ void tc_gemm1(
    const f16* __restrict__ A, int lda,
    const f16* __restrict__ B, int ldb,
    int K, float* acc)
{
    constexpr int WM = BM / 4, WN = BN / 2;
    constexpr int ROWB = CK * 2;
    constexpr int KG = CK / 8;            // 16B groups per row
    constexpr int SA = BM * ROWB;
    constexpr int SB = BN * ROWB;
    constexpr int STG = SA + SB;
    extern __shared__ char sm[];

    const int tid  = threadIdx.x;
    const int lane = tid & 31;
    const int warp = tid >> 5;
    const int wm = warp >> 1, wn = warp & 1;

    const int arow = ((lane >> 3) & 1) * 8 + (lane & 7);
    const int akg  = (lane >> 4) & 1;
    const int brow = ((lane >> 4) & 1) * 8 + (lane & 7);
    const int bkg  = (lane >> 3) & 1;

    #pragma unroll
    for (int i = 0; i < WM * WN / 32; i++) acc[i] = 0.f;

    const int nch = K / CK;

    auto load_chunk = [&](int i) {
        const int k0 = i * CK;
        const uint32_t st = smem_u32(sm + (i & 1) * STG);
        #pragma unroll
        for (int j = 0; j < BM * CK / 2048; j++) {     // 4 KB per 256-thread pass
            int idx = tid + j * 256;
            int r = idx / KG, kg = idx % KG;
            cp16(st + swz<ROWB>(r, kg), A + (size_t)r * lda + k0 + kg * 8);
        }
        #pragma unroll
        for (int j = 0; j < BN * CK / 2048; j++) {
            int idx = tid + j * 256;
            int r = idx / KG, kg = idx % KG;
            cp16(st + SA + swz<ROWB>(r, kg), B + (size_t)r * ldb + k0 + kg * 8);
        }
        CP_COMMIT();
    };

    load_chunk(0);

    for (int i = 0; i < nch; i++) {
        CP_WAIT(0);
        __syncthreads();
        if (i + 1 < nch) load_chunk(i + 1);

        const uint32_t st = smem_u32(sm + (i & 1) * STG);
        #pragma unroll
        for (int ks = 0; ks < CK / 16; ks++) {
            uint32_t a[WM / 16][4], b[WN / 16][4];
            #pragma unroll
            for (int im = 0; im < WM / 16; im++) {
                int row = wm * WM + im * 16 + arow;
                ldsm4(a[im], st + swz<ROWB>(row, ks * 2 + akg));
            }
            #pragma unroll
            for (int j2 = 0; j2 < WN / 16; j2++) {
                int n = wn * WN + j2 * 16 + brow;
                ldsm4(b[j2], st + SA + swz<ROWB>(n, ks * 2 + bkg));
            }
            #pragma unroll
            for (int im = 0; im < WM / 16; im++)
                #pragma unroll
                for (int jn = 0; jn < WN / 8; jn++)
                    mma16816(acc + (im * (WN / 8) + jn) * 4,
                             a[im], &b[jn >> 1][(jn & 1) * 2]);
        }
    }
}

// epilogue iteration: f(row, col, val) over this thread's fragment elements
template<int BM, int BN, typename F>
__device__ __forceinline__ void epi(const float* acc, F&& f) {
    constexpr int WM = BM / 4, WN = BN / 2;
    const int lane = threadIdx.x & 31;
    const int warp = threadIdx.x >> 5;
    const int wm = warp >> 1, wn = warp & 1;
    const int g = lane >> 2, tg = lane & 3;
    #pragma unroll
    for (int im = 0; im < WM / 16; im++)
        #pragma unroll
        for (int jn = 0; jn < WN / 8; jn++)
            #pragma unroll
            for (int r = 0; r < 4; r++) {
                int row = wm * WM + im * 16 + g + ((r & 2) ? 8 : 0);
                int col = wn * WN + jn * 8 + tg * 2 + (r & 1);
                f(row, col, acc[(im * (WN / 8) + jn) * 4 + r]);
            }
}

// BN=128/CK=64 kernels: stage (128+128)*128 = 32 KB, x2 = 64 KB
#define SMEM_G128  (2 * (128 + 128) * 128)
// proj additionally stages a 128x129 fp32 tile for the Vt transpose
#define SMEM_PROJ  (128 * 129 * 4 > SMEM_G128 ? 128 * 129 * 4 : SMEM_G128)
// unify: BN=64/CK=128, stage (128+64)*256 = 48 KB, x2 = 96 KB
#define SMEM_UNIFY (2 * (128 + 64) * 256)

// ---------------------------------------------------------------------------
// QKV projection (BM=128, BN=128, CK=64).
// z: 0 = k (scaled), 1 = q (scaled), 2 = v -> Vt (staged via smem, coalesced)
// ---------------------------------------------------------------------------
__global__ __launch_bounds__(256, 2) void proj_kernel() {
    const int n0 = blockIdx.x * 128;
    const int m0 = blockIdx.y * 128;
    const int z  = blockIdx.z;
    const f16* W = (z == 0) ? g_wk : (z == 1) ? g_wq : g_wv;

    float acc[64];
    tc_gemm1<128, 128, 64>(g_x + (size_t)m0 * E, E, W + (size_t)n0 * E, E, E, acc);

    if (z == 2) {
        extern __shared__ char sm[];
        float* smf = (float*)sm;              // 128 x 129 fp32 = 66 KB
        __syncthreads();
        epi<128, 128>(acc, [&](int row, int col, float v) {
            smf[row * 129 + col] = v;
        });
        __syncthreads();
        const int b = m0 >> 10, t_base = m0 & 1023;
        const int h = n0 >> 9,  ec_base = n0 & 511;
        const size_t vb = ((size_t)((b * H + h) * E + ec_base)) * T + t_base;
        const int tid = threadIdx.x;
        #pragma unroll
        for (int j = 0; j < 64; j++) {
            int idx = tid + j * 256;          // 16384 elements
            int ec_i = idx >> 7, t_i = idx & 127;
            g_vt[vb + (size_t)ec_i * T + t_i] = __float2half(smf[t_i * 129 + ec_i]);
        }
    } else {
        f16* D = (z == 0) ? g_k : g_q;
        epi<128, 128>(acc, [&](int row, int col, float v) {
            D[(size_t)(m0 + row) * NPROJ + n0 + col] = __float2half(v * QK_SCALE);
        });
    }
}

// ---------------------------------------------------------------------------
// Scores (BM=128 q, BN=128 k, CK=64): lower-triangle tiles only, q reversed.
// S stored fp16.
// ---------------------------------------------------------------------------
__global__ __launch_bounds__(256, 2) void scores_kernel() {
    const int k0 = blockIdx.x * 128;
    const int q0 = (int)(gridDim.y - 1 - blockIdx.y) * 128;
    if (k0 > q0) return;
    const int bh = blockIdx.z;
    const int b = bh >> 3, h = bh & 7;
    const size_t base = (size_t)b * T * NPROJ + (size_t)h * E;

    float acc[64];
    tc_gemm1<128, 128, 64>(g_q + base + (size_t)q0 * NPROJ, NPROJ,
                           g_k + base + (size_t)k0 * NPROJ, NPROJ, E, acc);

    f16* S = g_s + (size_t)bh * T * T;
    epi<128, 128>(acc, [&](int row, int col, float v) {
        S[(size_t)(q0 + row) * T + k0 + col] = __float2half(v);
    });
}

// ---------------------------------------------------------------------------
// Softmax: fp16 score loads, shuffle reductions, single fp16 prob output.
// Writes only k < roundup128(trow+1).
// ---------------------------------------------------------------------------
__global__ void softmax_kernel() {
    const int row = blockIdx.x;
    const int trow = row & 1023;
    const int kend = (trow & ~127) + 128;
    const f16* __restrict__ S = g_s + (size_t)row * T;
    f16* __restrict__ P = g_p + (size_t)row * T;
    const int tid = threadIdx.x;
    const int lane = tid & 31, warp = tid >> 5;
    __shared__ float red[8];

    const int base = tid * 4;
    f16 s4[4];
    *(uint2*)s4 = *(const uint2*)(S + base);
    float v[4];
    #pragma unroll
    for (int i = 0; i < 4; i++)
        v[i] = (base + i <= trow) ? __half2float(s4[i]) : NEG_INF;

    float m = fmaxf(fmaxf(v[0], v[1]), fmaxf(v[2], v[3]));
    #pragma unroll
    for (int o = 16; o > 0; o >>= 1) m = fmaxf(m, __shfl_xor_sync(~0u, m, o));
    if (lane == 0) red[warp] = m;
    __syncthreads();
    m = red[0];
    #pragma unroll
    for (int w = 1; w < 8; w++) m = fmaxf(m, red[w]);
    __syncthreads();

    float sum = 0.f;
    #pragma unroll
    for (int i = 0; i < 4; i++) { v[i] = __expf(v[i] - m); sum += v[i]; }
    #pragma unroll
    for (int o = 16; o > 0; o >>= 1) sum += __shfl_xor_sync(~0u, sum, o);
    if (lane == 0) red[warp] = sum;
    __syncthreads();
    sum = red[0];
    #pragma unroll
    for (int w = 1; w < 8; w++) sum += red[w];

    const float inv = 1.0f / sum;
    if (base < kend) {
        f16 p[4];
        #pragma unroll
        for (int i = 0; i < 4; i++) p[i] = __float2half(v[i] * inv);
        *(uint2*)(P + base) = *(const uint2*)p;
    }
}

// ---------------------------------------------------------------------------
// AV (BM=128 q, BN=128 e, CK=64): K truncated causally; q reversed.
// ---------------------------------------------------------------------------
__global__ __launch_bounds__(256, 2) void av_kernel() {
    const int n0 = blockIdx.x * 128;
    const int q0 = (int)(gridDim.y - 1 - blockIdx.y) * 128;
    const int bh = blockIdx.z;
    const int b = bh >> 3, h = bh & 7;
    const size_t pbase = (size_t)bh * T * T + (size_t)q0 * T;
    const size_t vbase = (size_t)bh * E * T + (size_t)n0 * T;

    float acc[64];
    tc_gemm1<128, 128, 64>(g_p + pbase, T, g_vt + vbase, T, q0 + 128, acc);

    epi<128, 128>(acc, [&](int row, int col, float v) {
        size_t o = (size_t)(b * T + q0 + row) * NPROJ + h * E + n0 + col;
        g_ao[o] = __float2half(v);
    });
}

// ---------------------------------------------------------------------------
// Unify (BM=128, BN=64, CK=128): grid 8x32 keeps the chip filled.
// out = AO @ wu^T + bu
// ---------------------------------------------------------------------------
__global__ __launch_bounds__(256, 2) void unify_kernel(const float* __restrict__ bu,
                                                       float* __restrict__ out) {
    const int n0 = blockIdx.x * 64;
    const int m0 = blockIdx.y * 128;

    float acc[32];
    tc_gemm1<128, 64, 128>(g_ao + (size_t)m0 * NPROJ, NPROJ,
                           g_wu + (size_t)n0 * NPROJ, NPROJ, NPROJ, acc);

    epi<128, 64>(acc, [&](int row, int col, float v) {
        out[(size_t)(m0 + row) * E + n0 + col] = v + bu[n0 + col];
    });
}

// ---------------------------------------------------------------------------
extern "C" void kernel_launch(void* const* d_in, const int* in_sizes, int n_in,
                              void* d_out, int out_size) {
    const float* x  = (const float*)d_in[0];
    const float* wk = (const float*)d_in[1];
    const float* wq = (const float*)d_in[2];
    const float* wv = (const float*)d_in[3];
    const float* wu = (const float*)d_in[4];
    const float* bu = (const float*)d_in[5];
    float* out = (float*)d_out;

    cudaFuncSetAttribute(proj_kernel,   cudaFuncAttributeMaxDynamicSharedMemorySize, SMEM_PROJ);
    cudaFuncSetAttribute(scores_kernel, cudaFuncAttributeMaxDynamicSharedMemorySize, SMEM_G128);
    cudaFuncSetAttribute(av_kernel,     cudaFuncAttributeMaxDynamicSharedMemorySize, SMEM_G128);
    cudaFuncSetAttribute(unify_kernel,  cudaFuncAttributeMaxDynamicSharedMemorySize, SMEM_UNIFY);

    split_all<<<dim3(MTOT * E / 1024, 5), 256>>>(x, wk, wq, wv, wu);

    proj_kernel  <<<dim3(NPROJ / 128, MTOT / 128, 3), 256, SMEM_PROJ>>>();
    scores_kernel<<<dim3(T / 128, T / 128, BH),        256, SMEM_G128>>>();
    softmax_kernel<<<BH * T, 256>>>();
    av_kernel    <<<dim3(E / 128, T / 128, BH),        256, SMEM_G128>>>();
    unify_kernel <<<dim3(E / 64, MTOT / 128),          256, SMEM_UNIFY>>>(bu, out);
}